// round 1
// baseline (speedup 1.0000x reference)
#include <cuda_runtime.h>
#include <math.h>
#include <stdint.h>

#define S_LEN 2048
#define HID   2048
#define NH    8
#define NKV   4
#define HD    256
#define QSCALE 0.0625f       // D^-0.5
#define INV_CAP 0.02f        // 1/50
#define CAP    50.0f

// ---- scratch (device globals; allocation inside kernel_launch is forbidden) ----
__device__ float g_q[(size_t)4096 * 2048];
__device__ float g_k[(size_t)4096 * 1024];
__device__ float g_v[(size_t)4096 * 1024];
__device__ float g_att[(size_t)4096 * 2048];
__device__ float g_linv[32768];

// =====================================================================
// SGEMM:  C[M,N] = A[M,K] @ B[N,K]^T     (both row-major, K-contiguous)
// 128x128 block, BK=8, 256 threads, 8x8 per thread, gmem prefetch.
// M,N divisible by 128; K divisible by 8.
// =====================================================================
__global__ __launch_bounds__(256) void sgemm_nt(
    const float* __restrict__ A, const float* __restrict__ B,
    float* __restrict__ C, int M, int N, int K)
{
    __shared__ float As[8][128];
    __shared__ float Bs[8][128];
    const int tid = threadIdx.x;
    const int tx = tid & 15, ty = tid >> 4;
    const int lr = tid >> 1;
    const int lc = (tid & 1) * 4;
    const float* Ab = A + (size_t)blockIdx.y * 128 * K;
    const float* Bb = B + (size_t)blockIdx.x * 128 * K;

    float acc[8][8];
#pragma unroll
    for (int i = 0; i < 8; i++)
#pragma unroll
        for (int j = 0; j < 8; j++) acc[i][j] = 0.f;

    float4 a4 = *(const float4*)(Ab + (size_t)lr * K + lc);
    float4 b4 = *(const float4*)(Bb + (size_t)lr * K + lc);

    for (int k0 = 0; k0 < K; k0 += 8) {
        __syncthreads();   // previous iteration's smem reads complete
        As[lc + 0][lr] = a4.x; As[lc + 1][lr] = a4.y;
        As[lc + 2][lr] = a4.z; As[lc + 3][lr] = a4.w;
        Bs[lc + 0][lr] = b4.x; Bs[lc + 1][lr] = b4.y;
        Bs[lc + 2][lr] = b4.z; Bs[lc + 3][lr] = b4.w;
        __syncthreads();
        if (k0 + 8 < K) {
            a4 = *(const float4*)(Ab + (size_t)lr * K + k0 + 8 + lc);
            b4 = *(const float4*)(Bb + (size_t)lr * K + k0 + 8 + lc);
        }
#pragma unroll
        for (int kk = 0; kk < 8; kk++) {
            float4 a0 = *(const float4*)&As[kk][ty * 4];
            float4 a1 = *(const float4*)&As[kk][64 + ty * 4];
            float4 b0 = *(const float4*)&Bs[kk][tx * 4];
            float4 b1 = *(const float4*)&Bs[kk][64 + tx * 4];
            float ra[8] = {a0.x, a0.y, a0.z, a0.w, a1.x, a1.y, a1.z, a1.w};
            float rb[8] = {b0.x, b0.y, b0.z, b0.w, b1.x, b1.y, b1.z, b1.w};
#pragma unroll
            for (int i = 0; i < 8; i++)
#pragma unroll
                for (int j = 0; j < 8; j++) acc[i][j] += ra[i] * rb[j];
        }
    }
    float* Cb = C + (size_t)(blockIdx.y * 128) * N + blockIdx.x * 128;
#pragma unroll
    for (int hi = 0; hi < 2; hi++)
#pragma unroll
        for (int i = 0; i < 4; i++) {
            int r = hi * 64 + ty * 4 + i;
#pragma unroll
            for (int hj = 0; hj < 2; hj++) {
                float4 v;
                v.x = acc[hi * 4 + i][hj * 4 + 0];
                v.y = acc[hi * 4 + i][hj * 4 + 1];
                v.z = acc[hi * 4 + i][hj * 4 + 2];
                v.w = acc[hi * 4 + i][hj * 4 + 3];
                *(float4*)(Cb + (size_t)r * N + hj * 64 + tx * 4) = v;
            }
        }
}

// =====================================================================
// RoPE, in place.  buf: [4096][nheads*256]; pos = n % 2048.
// =====================================================================
__global__ void rope_kernel(float* __restrict__ buf, const float* __restrict__ cosb,
                            const float* __restrict__ sinb, int nheads)
{
    int idx = blockIdx.x * blockDim.x + threadIdx.x;
    int total = 4096 * nheads * 128;
    if (idx >= total) return;
    int j = idx & 127;
    int h = (idx >> 7) % nheads;
    int n = idx / (128 * nheads);
    int t = n & (S_LEN - 1);
    size_t base = (size_t)n * (nheads * 256) + h * 256 + j;
    float x1 = buf[base];
    float x2 = buf[base + 128];
    float c = cosb[t * 128 + j];
    float s = sinb[t * 128 + j];
    buf[base]       = x1 * c - x2 * s;
    buf[base + 128] = x1 * s + x2 * c;
}

// =====================================================================
// Attention: one block per (b, h, 64-query tile). Single pass:
//   - score = tanh(q.k * scale / 50) * 50   (softcap)
//   - p~ = exp(score - 50) inside the causal sliding window, else 0
//     (scores are bounded by +-50, so no max-pass is needed; identical
//      math to reference softmax after normalization)
//   - write p~ to probs (normalized later), accumulate row sums and O.
// smem: Q[64][260], K/V[64][260], P^T[64][65]  (padded strides vs conflicts)
// =====================================================================
#define QROW 260
#define KS_OFF (64 * QROW)
#define PS_OFF (2 * 64 * QROW)
#define SM_FLOATS (PS_OFF + 64 * 65)

__global__ __launch_bounds__(256) void attn_kernel(
    const float* __restrict__ gq, const float* __restrict__ gk, const float* __restrict__ gv,
    float* __restrict__ probs, float* __restrict__ attn_out,
    float* __restrict__ gatt, float* __restrict__ linv)
{
    extern __shared__ float sm[];
    float* smQ  = sm;
    float* smKV = sm + KS_OFF;
    float* smP  = sm + PS_OFF;

    const int tid = threadIdx.x;
    const int tx = tid & 15, ty = tid >> 4;
    const int q0 = blockIdx.x * 64;
    const int h  = blockIdx.y;
    const int b  = blockIdx.z;
    const int hkv = h >> 1;   // rep = H/HKV = 2

    // load Q tile (pre-scaled)
    const float* qbase = gq + ((size_t)(b * S_LEN + q0)) * 2048 + h * 256;
#pragma unroll
    for (int it = 0; it < 16; it++) {
        int idx = it * 256 + tid;
        int r  = idx >> 6;
        int d4 = (idx & 63) << 2;
        float4 v = *(const float4*)(qbase + (size_t)r * 2048 + d4);
        float* dst = smQ + r * QROW + d4;
        dst[0] = v.x * QSCALE; dst[1] = v.y * QSCALE;
        dst[2] = v.z * QSCALE; dst[3] = v.w * QSCALE;
    }

    float4 o[4][4];
#pragma unroll
    for (int i = 0; i < 4; i++)
#pragma unroll
        for (int q = 0; q < 4; q++) o[i][q] = make_float4(0.f, 0.f, 0.f, 0.f);
    float lsum[4] = {0.f, 0.f, 0.f, 0.f};

    const int iglob0 = q0 + ty * 4;
    const int kstart = max(0, q0 - 1024);

    for (int kt0 = kstart; kt0 <= q0; kt0 += 64) {
        __syncthreads();  // smKV (prev V) and smP reuse
        const float* kbase = gk + ((size_t)(b * S_LEN + kt0)) * 1024 + hkv * 256;
#pragma unroll
        for (int it = 0; it < 16; it++) {
            int idx = it * 256 + tid;
            int c  = idx >> 6;
            int d4 = (idx & 63) << 2;
            *(float4*)(smKV + c * QROW + d4) =
                *(const float4*)(kbase + (size_t)c * 1024 + d4);
        }
        __syncthreads();

        float acc[4][4];
#pragma unroll
        for (int i = 0; i < 4; i++)
#pragma unroll
            for (int j = 0; j < 4; j++) acc[i][j] = 0.f;

#pragma unroll 4
        for (int d4 = 0; d4 < 64; d4++) {
            float4 qa[4], kb[4];
#pragma unroll
            for (int i = 0; i < 4; i++)
                qa[i] = *(const float4*)(smQ + (ty * 4 + i) * QROW + d4 * 4);
#pragma unroll
            for (int j = 0; j < 4; j++)
                kb[j] = *(const float4*)(smKV + (tx * 4 + j) * QROW + d4 * 4);
#pragma unroll
            for (int i = 0; i < 4; i++)
#pragma unroll
                for (int j = 0; j < 4; j++)
                    acc[i][j] += qa[i].x * kb[j].x + qa[i].y * kb[j].y +
                                 qa[i].z * kb[j].z + qa[i].w * kb[j].w;
        }

        // softcap + window mask + exp(score-50); emit probs~, P^T, row sums
#pragma unroll
        for (int i = 0; i < 4; i++) {
            int ig = iglob0 + i;
            float pr[4];
#pragma unroll
            for (int j = 0; j < 4; j++) {
                int jg = kt0 + tx * 4 + j;
                float x = acc[i][j] * INV_CAP;
                x = fminf(fmaxf(x, -15.f), 15.f);
                float e = __expf(2.f * x);
                float t = (e - 1.f) / (e + 1.f) * CAP;
                bool win = (jg <= ig) && (ig - jg < 1024);
                float p = win ? __expf(t - CAP) : 0.f;
                pr[j] = p;
                lsum[i] += p;
                smP[(tx * 4 + j) * 65 + ty * 4 + i] = p;
            }
            float4 pv = make_float4(pr[0], pr[1], pr[2], pr[3]);
            *(float4*)(probs + ((size_t)((b * NH + h) * S_LEN + ig)) * S_LEN +
                       kt0 + tx * 4) = pv;
        }
        __syncthreads();

        // V tile over smKV (row-major stride 256)
        const float* vbase = gv + ((size_t)(b * S_LEN + kt0)) * 1024 + hkv * 256;
#pragma unroll
        for (int it = 0; it < 16; it++) {
            int idx = it * 256 + tid;
            int c  = idx >> 6;
            int d4 = (idx & 63) << 2;
            *(float4*)(smKV + c * 256 + d4) =
                *(const float4*)(vbase + (size_t)c * 1024 + d4);
        }
        __syncthreads();

        // O += P~ @ V
#pragma unroll 2
        for (int c = 0; c < 64; c++) {
            float pa[4];
#pragma unroll
            for (int i = 0; i < 4; i++) pa[i] = smP[c * 65 + ty * 4 + i];
#pragma unroll
            for (int q = 0; q < 4; q++) {
                float4 v4 = *(const float4*)(smKV + c * 256 + q * 64 + tx * 4);
#pragma unroll
                for (int i = 0; i < 4; i++) {
                    o[i][q].x += pa[i] * v4.x;
                    o[i][q].y += pa[i] * v4.y;
                    o[i][q].z += pa[i] * v4.z;
                    o[i][q].w += pa[i] * v4.w;
                }
            }
        }
    }

    // row-sum butterfly across the 16 tx lanes (all lanes get the total)
#pragma unroll
    for (int i = 0; i < 4; i++) {
        float s = lsum[i];
        s += __shfl_xor_sync(0xffffffffu, s, 1, 16);
        s += __shfl_xor_sync(0xffffffffu, s, 2, 16);
        s += __shfl_xor_sync(0xffffffffu, s, 4, 16);
        s += __shfl_xor_sync(0xffffffffu, s, 8, 16);
        lsum[i] = 1.f / s;
    }
    if (tx == 0) {
#pragma unroll
        for (int i = 0; i < 4; i++)
            linv[(size_t)(b * NH + h) * S_LEN + iglob0 + i] = lsum[i];
    }
#pragma unroll
    for (int i = 0; i < 4; i++) {
        size_t row = (size_t)(iglob0 + i);
        float inv = lsum[i];
        float* ao = attn_out + ((size_t)(b * NH + h) * S_LEN + row) * 256;
        float* ga = gatt + ((size_t)b * S_LEN + row) * 2048 + h * 256;
#pragma unroll
        for (int q = 0; q < 4; q++) {
            float4 v = o[i][q];
            v.x *= inv; v.y *= inv; v.z *= inv; v.w *= inv;
            *(float4*)(ao + q * 64 + tx * 4) = v;
            *(float4*)(ga + q * 64 + tx * 4) = v;
        }
    }
}

// =====================================================================
// Scale the banded window region of probs by 1/l (out-of-window is 0).
// One block per (b,h,i) row.
// =====================================================================
__global__ void norm_probs_kernel(float* __restrict__ probs,
                                  const float* __restrict__ linv)
{
    int row = blockIdx.x;           // 0..32767 = (b*8+h)*2048 + i
    int i = row & (S_LEN - 1);
    float inv = linv[row];
    float4* p = (float4*)(probs + (size_t)row * S_LEN);
    int c0 = max(0, i - 1023) >> 2;
    for (int c = c0 + (int)threadIdx.x; (c << 2) <= i; c += blockDim.x) {
        float4 v = p[c];
        v.x *= inv; v.y *= inv; v.z *= inv; v.w *= inv;
        p[c] = v;
    }
}

// =====================================================================
// Outputs concatenated in tuple order:
//   out  [2,2048,2048]           @ 0
//   probs[2,8,2048,2048]         @ 8388608
//   attn [2,8,2048,256]          @ 75497472
// =====================================================================
extern "C" void kernel_launch(void* const* d_in, const int* in_sizes, int n_in,
                              void* d_out, int out_size)
{
    const float* hs = (const float*)d_in[0];
    const float* fc = (const float*)d_in[1];
    const float* fs = (const float*)d_in[2];
    /* d_in[3] = mask — implied analytically (causal + sliding window) */
    const float* wq = (const float*)d_in[4];
    const float* wk = (const float*)d_in[5];
    const float* wv = (const float*)d_in[6];
    const float* wo = (const float*)d_in[7];

    float* out   = (float*)d_out;
    float* probs = out + 8388608ull;
    float* attn  = probs + 67108864ull;

    float *gq, *gk, *gv, *gatt, *glinv;
    cudaGetSymbolAddress((void**)&gq,   g_q);
    cudaGetSymbolAddress((void**)&gk,   g_k);
    cudaGetSymbolAddress((void**)&gv,   g_v);
    cudaGetSymbolAddress((void**)&gatt, g_att);
    cudaGetSymbolAddress((void**)&glinv, g_linv);

    cudaFuncSetAttribute(attn_kernel,
                         cudaFuncAttributeMaxDynamicSharedMemorySize,
                         SM_FLOATS * 4);

    dim3 blk(256);
    // QKV projections
    sgemm_nt<<<dim3(2048 / 128, 4096 / 128), blk>>>(hs, wq, gq, 4096, 2048, 2048);
    sgemm_nt<<<dim3(1024 / 128, 4096 / 128), blk>>>(hs, wk, gk, 4096, 1024, 2048);
    sgemm_nt<<<dim3(1024 / 128, 4096 / 128), blk>>>(hs, wv, gv, 4096, 1024, 2048);
    // RoPE on q (8 heads) and k (4 heads)
    rope_kernel<<<(4096 * 8 * 128) / 256, 256>>>(gq, fc, fs, 8);
    rope_kernel<<<(4096 * 4 * 128) / 256, 256>>>(gk, fc, fs, 4);
    // probs: zero everywhere, attention fills the banded window
    cudaMemsetAsync(probs, 0, 67108864ull * sizeof(float));
    attn_kernel<<<dim3(32, 8, 2), blk, SM_FLOATS * 4>>>(gq, gk, gv, probs, attn,
                                                        gatt, glinv);
    norm_probs_kernel<<<32768, 256>>>(probs, glinv);
    // output projection
    sgemm_nt<<<dim3(2048 / 128, 4096 / 128), blk>>>(gatt, wo, out, 4096, 2048, 2048);
}

// round 4
// speedup vs baseline: 1.4152x; 1.4152x over previous
#include <cuda_runtime.h>
#include <cuda_bf16.h>
#include <math.h>
#include <stdint.h>

#define S_LEN 2048
#define HID   2048
#define NH    8
#define NKV   4
#define HD    256
#define QSCALE 0.0625f       // D^-0.5
#define INV_CAP 0.02f        // 1/50
#define CAP    50.0f

// ---- fp32 scratch ----
__device__ float g_q[(size_t)4096 * 2048];
__device__ float g_k[(size_t)4096 * 1024];
__device__ float g_v[(size_t)4096 * 1024];
__device__ float g_att[(size_t)4096 * 2048];
__device__ float g_linv[32768];

// ---- bf16 split scratch (uint4 arrays => 16B alignment guaranteed) ----
__device__ uint4 g_hs_h[(size_t)4096 * 2048 / 8];
__device__ uint4 g_hs_l[(size_t)4096 * 2048 / 8];
__device__ uint4 g_att_h[(size_t)4096 * 2048 / 8];
__device__ uint4 g_att_l[(size_t)4096 * 2048 / 8];
__device__ uint4 g_wq_h[(size_t)2048 * 2048 / 8];
__device__ uint4 g_wq_l[(size_t)2048 * 2048 / 8];
__device__ uint4 g_wk_h[(size_t)1024 * 2048 / 8];
__device__ uint4 g_wk_l[(size_t)1024 * 2048 / 8];
__device__ uint4 g_wv_h[(size_t)1024 * 2048 / 8];
__device__ uint4 g_wv_l[(size_t)1024 * 2048 / 8];
__device__ uint4 g_wo_h[(size_t)2048 * 2048 / 8];
__device__ uint4 g_wo_l[(size_t)2048 * 2048 / 8];

// =====================================================================
// helpers (baseline PTX only: cp.async / ldmatrix / mma.sync)
// =====================================================================
__device__ __forceinline__ uint32_t smem_u32(const void* p) {
    uint32_t a;
    asm("{ .reg .u64 t; cvta.to.shared.u64 t, %1; cvt.u32.u64 %0, t; }"
        : "=r"(a) : "l"(p));
    return a;
}
__device__ __forceinline__ void cp_async16(uint32_t saddr, const void* gaddr) {
    asm volatile("cp.async.cg.shared.global [%0], [%1], 16;"
                 :: "r"(saddr), "l"(gaddr) : "memory");
}
#define CP_COMMIT() asm volatile("cp.async.commit_group;" ::: "memory")
#define CP_WAIT1()  asm volatile("cp.async.wait_group 1;" ::: "memory")

__device__ __forceinline__ void ldsm_x4(uint32_t* r, uint32_t addr) {
    asm volatile("ldmatrix.sync.aligned.m8n8.x4.shared.b16 {%0,%1,%2,%3}, [%4];"
                 : "=r"(r[0]), "=r"(r[1]), "=r"(r[2]), "=r"(r[3]) : "r"(addr));
}
// B fragment for row.col mma from [n][k] k-contiguous smem: NON-transposed
// ldmatrix (b0 must hold two consecutive k of one n; .trans was the R3 bug).
__device__ __forceinline__ void ldsm_x2(uint32_t* r, uint32_t addr) {
    asm volatile("ldmatrix.sync.aligned.m8n8.x2.shared.b16 {%0,%1}, [%2];"
                 : "=r"(r[0]), "=r"(r[1]) : "r"(addr));
}
__device__ __forceinline__ void mma16816(float* c, const uint32_t* a,
                                         const uint32_t* b) {
    asm volatile(
        "mma.sync.aligned.m16n8k16.row.col.f32.bf16.bf16.f32 "
        "{%0,%1,%2,%3}, {%4,%5,%6,%7}, {%8,%9}, {%0,%1,%2,%3};"
        : "+f"(c[0]), "+f"(c[1]), "+f"(c[2]), "+f"(c[3])
        : "r"(a[0]), "r"(a[1]), "r"(a[2]), "r"(a[3]), "r"(b[0]), "r"(b[1]));
}

// =====================================================================
// split fp32 -> (hi, lo) bf16
// =====================================================================
__global__ void split_kernel(const float* __restrict__ x,
                             __nv_bfloat16* __restrict__ hi,
                             __nv_bfloat16* __restrict__ lo, int n4)
{
    int i = blockIdx.x * blockDim.x + threadIdx.x;
    if (i >= n4) return;
    float4 v = ((const float4*)x)[i];
    __nv_bfloat16 h0 = __float2bfloat16(v.x);
    __nv_bfloat16 h1 = __float2bfloat16(v.y);
    __nv_bfloat16 h2 = __float2bfloat16(v.z);
    __nv_bfloat16 h3 = __float2bfloat16(v.w);
    __nv_bfloat16 l0 = __float2bfloat16(v.x - __bfloat162float(h0));
    __nv_bfloat16 l1 = __float2bfloat16(v.y - __bfloat162float(h1));
    __nv_bfloat16 l2 = __float2bfloat16(v.z - __bfloat162float(h2));
    __nv_bfloat16 l3 = __float2bfloat16(v.w - __bfloat162float(h3));
    __nv_bfloat162* h2p = (__nv_bfloat162*)hi;
    __nv_bfloat162* l2p = (__nv_bfloat162*)lo;
    h2p[2 * i]     = __halves2bfloat162(h0, h1);
    h2p[2 * i + 1] = __halves2bfloat162(h2, h3);
    l2p[2 * i]     = __halves2bfloat162(l0, l1);
    l2p[2 * i + 1] = __halves2bfloat162(l2, l3);
}

// =====================================================================
// HMMA GEMM:  C[M,N] = (Ah+Al)[M,K] @ (Bh+Bl)[N,K]^T   (fp32 out)
// 3-product split: hh + hl + lh  (ll dropped, ~2^-16 relative).
// CTA tile 128x128, K-chunk 32, 8 warps (2x4), warp tile 64x32,
// cp.async 3-stage pipeline, padded 80B smem rows.
// =====================================================================
#define STAGES 3
#define TILE_B 10240                 // 128 rows * 80 bytes
#define STAGE_B (4 * TILE_B)         // Ah | Al | Bh | Bl
#define GEMM_SMEM (STAGES * STAGE_B) // 122880

__device__ __forceinline__ void issue_stage(
    uint32_t sb, int c, int tid, int m0, int n0, int K,
    const __nv_bfloat16* Ah, const __nv_bfloat16* Al,
    const __nv_bfloat16* Bh, const __nv_bfloat16* Bl)
{
    uint32_t st = sb + (uint32_t)(c % STAGES) * STAGE_B;
    int k0 = c * 32;
#pragma unroll
    for (int half = 0; half < 2; half++) {
        int idx = tid + half * 256;
        int row = idx >> 2;
        int seg = idx & 3;
        uint32_t so = (uint32_t)(row * 80 + seg * 16);
        size_t ga = (size_t)(m0 + row) * K + k0 + seg * 8;
        size_t gb = (size_t)(n0 + row) * K + k0 + seg * 8;
        cp_async16(st + so,              Ah + ga);
        cp_async16(st + TILE_B + so,     Al + ga);
        cp_async16(st + 2 * TILE_B + so, Bh + gb);
        cp_async16(st + 3 * TILE_B + so, Bl + gb);
    }
    CP_COMMIT();
}

__global__ __launch_bounds__(256, 1) void gemm_hmma(
    const __nv_bfloat16* __restrict__ Ah, const __nv_bfloat16* __restrict__ Al,
    const __nv_bfloat16* __restrict__ Bh, const __nv_bfloat16* __restrict__ Bl,
    float* __restrict__ C, int M, int N, int K)
{
    extern __shared__ __align__(128) char smem[];
    const uint32_t sb = smem_u32(smem);
    const int tid = threadIdx.x;
    const int wid = tid >> 5, lane = tid & 31;
    const int wm = wid >> 2, wn = wid & 3;
    const int m0 = blockIdx.y * 128, n0 = blockIdx.x * 128;

    float acc[4][4][4];
#pragma unroll
    for (int mi = 0; mi < 4; mi++)
#pragma unroll
        for (int ni = 0; ni < 4; ni++)
#pragma unroll
            for (int r = 0; r < 4; r++) acc[mi][ni][r] = 0.f;

    const int NC = K >> 5;
    issue_stage(sb, 0, tid, m0, n0, K, Ah, Al, Bh, Bl);
    issue_stage(sb, 1, tid, m0, n0, K, Ah, Al, Bh, Bl);

    // per-lane ldmatrix base offsets (byte offsets within a tile)
    const uint32_t aoff = (uint32_t)((wm * 64 + (lane & 15)) * 80 +
                                     (lane >> 4) * 16);
    const uint32_t boff = (uint32_t)((wn * 32 + (lane & 7)) * 80 +
                                     ((lane >> 3) & 1) * 16);

    for (int c = 0; c < NC; c++) {
        CP_WAIT1();
        __syncthreads();
        const uint32_t st = sb + (uint32_t)(c % STAGES) * STAGE_B;
        const uint32_t aA = st + aoff;               // A_hi tile
        const uint32_t aB = st + 2 * TILE_B + boff;  // B_hi tile

#pragma unroll
        for (int ks = 0; ks < 2; ks++) {
            uint32_t ah[4][4], al[4][4], bh[4][2], bl[4][2];
#pragma unroll
            for (int mi = 0; mi < 4; mi++)
                ldsm_x4(ah[mi], aA + mi * (16 * 80) + ks * 32);
#pragma unroll
            for (int ni = 0; ni < 4; ni++) {
                ldsm_x2(bh[ni], aB + ni * (8 * 80) + ks * 32);
                ldsm_x2(bl[ni], aB + TILE_B + ni * (8 * 80) + ks * 32);
            }
#pragma unroll
            for (int mi = 0; mi < 4; mi++)
#pragma unroll
                for (int ni = 0; ni < 4; ni++) {
                    mma16816(acc[mi][ni], ah[mi], bh[ni]);
                    mma16816(acc[mi][ni], ah[mi], bl[ni]);
                }
#pragma unroll
            for (int mi = 0; mi < 4; mi++)
                ldsm_x4(al[mi], aA + TILE_B + mi * (16 * 80) + ks * 32);
#pragma unroll
            for (int mi = 0; mi < 4; mi++)
#pragma unroll
                for (int ni = 0; ni < 4; ni++)
                    mma16816(acc[mi][ni], al[mi], bh[ni]);
        }
        __syncthreads();
        if (c + 2 < NC)
            issue_stage(sb, c + 2, tid, m0, n0, K, Ah, Al, Bh, Bl);
    }

    // epilogue
    const int gr = lane >> 2, cn = lane & 3;
#pragma unroll
    for (int mi = 0; mi < 4; mi++) {
        int r = m0 + wm * 64 + mi * 16 + gr;
#pragma unroll
        for (int ni = 0; ni < 4; ni++) {
            int col = n0 + wn * 32 + ni * 8 + cn * 2;
            *(float2*)(C + (size_t)r * N + col) =
                make_float2(acc[mi][ni][0], acc[mi][ni][1]);
            *(float2*)(C + (size_t)(r + 8) * N + col) =
                make_float2(acc[mi][ni][2], acc[mi][ni][3]);
        }
    }
}

// =====================================================================
// RoPE, in place.  buf: [4096][nheads*256]; pos = n % 2048.
// =====================================================================
__global__ void rope_kernel(float* __restrict__ buf, const float* __restrict__ cosb,
                            const float* __restrict__ sinb, int nheads)
{
    int idx = blockIdx.x * blockDim.x + threadIdx.x;
    int total = 4096 * nheads * 128;
    if (idx >= total) return;
    int j = idx & 127;
    int h = (idx >> 7) % nheads;
    int n = idx / (128 * nheads);
    int t = n & (S_LEN - 1);
    size_t base = (size_t)n * (nheads * 256) + h * 256 + j;
    float x1 = buf[base];
    float x2 = buf[base + 128];
    float c = cosb[t * 128 + j];
    float s = sinb[t * 128 + j];
    buf[base]       = x1 * c - x2 * s;
    buf[base + 128] = x1 * s + x2 * c;
}

// =====================================================================
// Attention (fp32): one block per (b, h, 64-query tile). Single pass.
// =====================================================================
#define QROW 260
#define KS_OFF (64 * QROW)
#define PS_OFF (2 * 64 * QROW)
#define SM_FLOATS (PS_OFF + 64 * 65)

__global__ __launch_bounds__(256) void attn_kernel(
    const float* __restrict__ gq, const float* __restrict__ gk, const float* __restrict__ gv,
    float* __restrict__ probs, float* __restrict__ attn_out,
    float* __restrict__ gatt, float* __restrict__ linv)
{
    extern __shared__ float sm[];
    float* smQ  = sm;
    float* smKV = sm + KS_OFF;
    float* smP  = sm + PS_OFF;

    const int tid = threadIdx.x;
    const int tx = tid & 15, ty = tid >> 4;
    const int q0 = blockIdx.x * 64;
    const int h  = blockIdx.y;
    const int b  = blockIdx.z;
    const int hkv = h >> 1;

    const float* qbase = gq + ((size_t)(b * S_LEN + q0)) * 2048 + h * 256;
#pragma unroll
    for (int it = 0; it < 16; it++) {
        int idx = it * 256 + tid;
        int r  = idx >> 6;
        int d4 = (idx & 63) << 2;
        float4 v = *(const float4*)(qbase + (size_t)r * 2048 + d4);
        float* dst = smQ + r * QROW + d4;
        dst[0] = v.x * QSCALE; dst[1] = v.y * QSCALE;
        dst[2] = v.z * QSCALE; dst[3] = v.w * QSCALE;
    }

    float4 o[4][4];
#pragma unroll
    for (int i = 0; i < 4; i++)
#pragma unroll
        for (int q = 0; q < 4; q++) o[i][q] = make_float4(0.f, 0.f, 0.f, 0.f);
    float lsum[4] = {0.f, 0.f, 0.f, 0.f};

    const int iglob0 = q0 + ty * 4;
    const int kstart = max(0, q0 - 1024);

    for (int kt0 = kstart; kt0 <= q0; kt0 += 64) {
        __syncthreads();
        const float* kbase = gk + ((size_t)(b * S_LEN + kt0)) * 1024 + hkv * 256;
#pragma unroll
        for (int it = 0; it < 16; it++) {
            int idx = it * 256 + tid;
            int c  = idx >> 6;
            int d4 = (idx & 63) << 2;
            *(float4*)(smKV + c * QROW + d4) =
                *(const float4*)(kbase + (size_t)c * 1024 + d4);
        }
        __syncthreads();

        float acc[4][4];
#pragma unroll
        for (int i = 0; i < 4; i++)
#pragma unroll
            for (int j = 0; j < 4; j++) acc[i][j] = 0.f;

#pragma unroll 4
        for (int d4 = 0; d4 < 64; d4++) {
            float4 qa[4], kb[4];
#pragma unroll
            for (int i = 0; i < 4; i++)
                qa[i] = *(const float4*)(smQ + (ty * 4 + i) * QROW + d4 * 4);
#pragma unroll
            for (int j = 0; j < 4; j++)
                kb[j] = *(const float4*)(smKV + (tx * 4 + j) * QROW + d4 * 4);
#pragma unroll
            for (int i = 0; i < 4; i++)
#pragma unroll
                for (int j = 0; j < 4; j++)
                    acc[i][j] += qa[i].x * kb[j].x + qa[i].y * kb[j].y +
                                 qa[i].z * kb[j].z + qa[i].w * kb[j].w;
        }

#pragma unroll
        for (int i = 0; i < 4; i++) {
            int ig = iglob0 + i;
            float pr[4];
#pragma unroll
            for (int j = 0; j < 4; j++) {
                int jg = kt0 + tx * 4 + j;
                float x = acc[i][j] * INV_CAP;
                x = fminf(fmaxf(x, -15.f), 15.f);
                float e = __expf(2.f * x);
                float t = (e - 1.f) / (e + 1.f) * CAP;
                bool win = (jg <= ig) && (ig - jg < 1024);
                float p = win ? __expf(t - CAP) : 0.f;
                pr[j] = p;
                lsum[i] += p;
                smP[(tx * 4 + j) * 65 + ty * 4 + i] = p;
            }
            float4 pv = make_float4(pr[0], pr[1], pr[2], pr[3]);
            *(float4*)(probs + ((size_t)((b * NH + h) * S_LEN + ig)) * S_LEN +
                       kt0 + tx * 4) = pv;
        }
        __syncthreads();

        const float* vbase = gv + ((size_t)(b * S_LEN + kt0)) * 1024 + hkv * 256;
#pragma unroll
        for (int it = 0; it < 16; it++) {
            int idx = it * 256 + tid;
            int c  = idx >> 6;
            int d4 = (idx & 63) << 2;
            *(float4*)(smKV + c * 256 + d4) =
                *(const float4*)(vbase + (size_t)c * 1024 + d4);
        }
        __syncthreads();

#pragma unroll 2
        for (int c = 0; c < 64; c++) {
            float pa[4];
#pragma unroll
            for (int i = 0; i < 4; i++) pa[i] = smP[c * 65 + ty * 4 + i];
#pragma unroll
            for (int q = 0; q < 4; q++) {
                float4 v4 = *(const float4*)(smKV + c * 256 + q * 64 + tx * 4);
#pragma unroll
                for (int i = 0; i < 4; i++) {
                    o[i][q].x += pa[i] * v4.x;
                    o[i][q].y += pa[i] * v4.y;
                    o[i][q].z += pa[i] * v4.z;
                    o[i][q].w += pa[i] * v4.w;
                }
            }
        }
    }

#pragma unroll
    for (int i = 0; i < 4; i++) {
        float s = lsum[i];
        s += __shfl_xor_sync(0xffffffffu, s, 1, 16);
        s += __shfl_xor_sync(0xffffffffu, s, 2, 16);
        s += __shfl_xor_sync(0xffffffffu, s, 4, 16);
        s += __shfl_xor_sync(0xffffffffu, s, 8, 16);
        lsum[i] = 1.f / s;
    }
    if (tx == 0) {
#pragma unroll
        for (int i = 0; i < 4; i++)
            linv[(size_t)(b * NH + h) * S_LEN + iglob0 + i] = lsum[i];
    }
#pragma unroll
    for (int i = 0; i < 4; i++) {
        size_t row = (size_t)(iglob0 + i);
        float inv = lsum[i];
        float* ao = attn_out + ((size_t)(b * NH + h) * S_LEN + row) * 256;
        float* ga = gatt + ((size_t)b * S_LEN + row) * 2048 + h * 256;
#pragma unroll
        for (int q = 0; q < 4; q++) {
            float4 v = o[i][q];
            v.x *= inv; v.y *= inv; v.z *= inv; v.w *= inv;
            *(float4*)(ao + q * 64 + tx * 4) = v;
            *(float4*)(ga + q * 64 + tx * 4) = v;
        }
    }
}

// =====================================================================
// Normalize the banded window region of probs by 1/l.
// =====================================================================
__global__ void norm_probs_kernel(float* __restrict__ probs,
                                  const float* __restrict__ linv)
{
    int row = blockIdx.x;
    int i = row & (S_LEN - 1);
    float inv = linv[row];
    float4* p = (float4*)(probs + (size_t)row * S_LEN);
    int c0 = max(0, i - 1023) >> 2;
    for (int c = c0 + (int)threadIdx.x; (c << 2) <= i; c += blockDim.x) {
        float4 v = p[c];
        v.x *= inv; v.y *= inv; v.z *= inv; v.w *= inv;
        p[c] = v;
    }
}

// =====================================================================
// Outputs concatenated in tuple order:
//   out[2,2048,2048] @0 | probs[2,8,2048,2048] @8388608 | attn @75497472
// =====================================================================
extern "C" void kernel_launch(void* const* d_in, const int* in_sizes, int n_in,
                              void* d_out, int out_size)
{
    const float* hs = (const float*)d_in[0];
    const float* fc = (const float*)d_in[1];
    const float* fs = (const float*)d_in[2];
    const float* wq = (const float*)d_in[4];
    const float* wk = (const float*)d_in[5];
    const float* wv = (const float*)d_in[6];
    const float* wo = (const float*)d_in[7];

    float* out   = (float*)d_out;
    float* probs = out + 8388608ull;
    float* attn  = probs + 67108864ull;

    float *gq, *gk, *gv, *gatt, *glinv;
    cudaGetSymbolAddress((void**)&gq,   g_q);
    cudaGetSymbolAddress((void**)&gk,   g_k);
    cudaGetSymbolAddress((void**)&gv,   g_v);
    cudaGetSymbolAddress((void**)&gatt, g_att);
    cudaGetSymbolAddress((void**)&glinv, g_linv);

    void *hsh, *hsl, *atth, *attl, *wqh, *wql, *wkh, *wkl, *wvh, *wvl, *woh, *wol;
    cudaGetSymbolAddress(&hsh, g_hs_h);  cudaGetSymbolAddress(&hsl, g_hs_l);
    cudaGetSymbolAddress(&atth, g_att_h); cudaGetSymbolAddress(&attl, g_att_l);
    cudaGetSymbolAddress(&wqh, g_wq_h);  cudaGetSymbolAddress(&wql, g_wq_l);
    cudaGetSymbolAddress(&wkh, g_wk_h);  cudaGetSymbolAddress(&wkl, g_wk_l);
    cudaGetSymbolAddress(&wvh, g_wv_h);  cudaGetSymbolAddress(&wvl, g_wv_l);
    cudaGetSymbolAddress(&woh, g_wo_h);  cudaGetSymbolAddress(&wol, g_wo_l);

    cudaFuncSetAttribute(attn_kernel,
                         cudaFuncAttributeMaxDynamicSharedMemorySize, SM_FLOATS * 4);
    cudaFuncSetAttribute(gemm_hmma,
                         cudaFuncAttributeMaxDynamicSharedMemorySize, GEMM_SMEM);

    // splits: hs + all weights
    split_kernel<<<8192, 256>>>(hs, (__nv_bfloat16*)hsh, (__nv_bfloat16*)hsl, 2097152);
    split_kernel<<<4096, 256>>>(wq, (__nv_bfloat16*)wqh, (__nv_bfloat16*)wql, 1048576);
    split_kernel<<<2048, 256>>>(wk, (__nv_bfloat16*)wkh, (__nv_bfloat16*)wkl, 524288);
    split_kernel<<<2048, 256>>>(wv, (__nv_bfloat16*)wvh, (__nv_bfloat16*)wvl, 524288);
    split_kernel<<<4096, 256>>>(wo, (__nv_bfloat16*)woh, (__nv_bfloat16*)wol, 1048576);

    // QKV projections on tensor cores (HMMA)
    gemm_hmma<<<dim3(2048 / 128, 4096 / 128), 256, GEMM_SMEM>>>(
        (const __nv_bfloat16*)hsh, (const __nv_bfloat16*)hsl,
        (const __nv_bfloat16*)wqh, (const __nv_bfloat16*)wql, gq, 4096, 2048, 2048);
    gemm_hmma<<<dim3(1024 / 128, 4096 / 128), 256, GEMM_SMEM>>>(
        (const __nv_bfloat16*)hsh, (const __nv_bfloat16*)hsl,
        (const __nv_bfloat16*)wkh, (const __nv_bfloat16*)wkl, gk, 4096, 1024, 2048);
    gemm_hmma<<<dim3(1024 / 128, 4096 / 128), 256, GEMM_SMEM>>>(
        (const __nv_bfloat16*)hsh, (const __nv_bfloat16*)hsl,
        (const __nv_bfloat16*)wvh, (const __nv_bfloat16*)wvl, gv, 4096, 1024, 2048);

    // RoPE
    rope_kernel<<<(4096 * 8 * 128) / 256, 256>>>(gq, fc, fs, 8);
    rope_kernel<<<(4096 * 4 * 128) / 256, 256>>>(gk, fc, fs, 4);

    // attention
    cudaMemsetAsync(probs, 0, 67108864ull * sizeof(float));
    attn_kernel<<<dim3(32, 8, 2), 256, SM_FLOATS * 4>>>(gq, gk, gv, probs, attn,
                                                        gatt, glinv);
    norm_probs_kernel<<<32768, 256>>>(probs, glinv);

    // output projection
    split_kernel<<<8192, 256>>>(gatt, (__nv_bfloat16*)atth, (__nv_bfloat16*)attl, 2097152);
    gemm_hmma<<<dim3(2048 / 128, 4096 / 128), 256, GEMM_SMEM>>>(
        (const __nv_bfloat16*)atth, (const __nv_bfloat16*)attl,
        (const __nv_bfloat16*)woh, (const __nv_bfloat16*)wol, out, 4096, 2048, 2048);
}

// round 5
// speedup vs baseline: 2.2789x; 1.6104x over previous
#include <cuda_runtime.h>
#include <cuda_bf16.h>
#include <math.h>
#include <stdint.h>

#define S_LEN 2048
#define HID   2048
#define NH    8
#define NKV   4
#define HD    256
#define QSCALE 0.0625f       // D^-0.5
#define INV_CAP 0.02f        // 1/50
#define CAP    50.0f

// ---- fp32 scratch ----
__device__ float g_q[(size_t)4096 * 2048];
__device__ float g_k[(size_t)4096 * 1024];
__device__ float g_v[(size_t)4096 * 1024];
__device__ float g_linv[32768];

// ---- bf16 split scratch (uint4 arrays => 16B alignment) ----
__device__ uint4 g_hs_h[(size_t)4096 * 2048 / 8];
__device__ uint4 g_hs_l[(size_t)4096 * 2048 / 8];
__device__ uint4 g_att_h[(size_t)4096 * 2048 / 8];
__device__ uint4 g_att_l[(size_t)4096 * 2048 / 8];
__device__ uint4 g_wq_h[(size_t)2048 * 2048 / 8];
__device__ uint4 g_wq_l[(size_t)2048 * 2048 / 8];
__device__ uint4 g_wk_h[(size_t)1024 * 2048 / 8];
__device__ uint4 g_wk_l[(size_t)1024 * 2048 / 8];
__device__ uint4 g_wv_h[(size_t)1024 * 2048 / 8];
__device__ uint4 g_wv_l[(size_t)1024 * 2048 / 8];
__device__ uint4 g_wo_h[(size_t)2048 * 2048 / 8];
__device__ uint4 g_wo_l[(size_t)2048 * 2048 / 8];
// bf16 split q/k/v for HMMA attention
__device__ uint4 g_qh[(size_t)4096 * 2048 / 8];
__device__ uint4 g_ql[(size_t)4096 * 2048 / 8];
__device__ uint4 g_kh[(size_t)4096 * 1024 / 8];
__device__ uint4 g_kl[(size_t)4096 * 1024 / 8];
__device__ uint4 g_vh[(size_t)4096 * 1024 / 8];
__device__ uint4 g_vl[(size_t)4096 * 1024 / 8];

// =====================================================================
// helpers (baseline PTX only: cp.async / ldmatrix / mma.sync)
// =====================================================================
__device__ __forceinline__ uint32_t smem_u32(const void* p) {
    uint32_t a;
    asm("{ .reg .u64 t; cvta.to.shared.u64 t, %1; cvt.u32.u64 %0, t; }"
        : "=r"(a) : "l"(p));
    return a;
}
__device__ __forceinline__ void cp_async16(uint32_t saddr, const void* gaddr) {
    asm volatile("cp.async.cg.shared.global [%0], [%1], 16;"
                 :: "r"(saddr), "l"(gaddr) : "memory");
}
#define CP_COMMIT() asm volatile("cp.async.commit_group;" ::: "memory")
#define CP_WAIT1()  asm volatile("cp.async.wait_group 1;" ::: "memory")
#define CP_WAIT0()  asm volatile("cp.async.wait_group 0;" ::: "memory")

__device__ __forceinline__ void ldsm_x4(uint32_t* r, uint32_t addr) {
    asm volatile("ldmatrix.sync.aligned.m8n8.x4.shared.b16 {%0,%1,%2,%3}, [%4];"
                 : "=r"(r[0]), "=r"(r[1]), "=r"(r[2]), "=r"(r[3]) : "r"(addr));
}
__device__ __forceinline__ void ldsm_x4t(uint32_t* r, uint32_t addr) {
    asm volatile("ldmatrix.sync.aligned.m8n8.x4.trans.shared.b16 {%0,%1,%2,%3}, [%4];"
                 : "=r"(r[0]), "=r"(r[1]), "=r"(r[2]), "=r"(r[3]) : "r"(addr));
}
__device__ __forceinline__ void ldsm_x2(uint32_t* r, uint32_t addr) {
    asm volatile("ldmatrix.sync.aligned.m8n8.x2.shared.b16 {%0,%1}, [%2];"
                 : "=r"(r[0]), "=r"(r[1]) : "r"(addr));
}
__device__ __forceinline__ void mma16816(float* c, const uint32_t* a,
                                         const uint32_t* b) {
    asm volatile(
        "mma.sync.aligned.m16n8k16.row.col.f32.bf16.bf16.f32 "
        "{%0,%1,%2,%3}, {%4,%5,%6,%7}, {%8,%9}, {%0,%1,%2,%3};"
        : "+f"(c[0]), "+f"(c[1]), "+f"(c[2]), "+f"(c[3])
        : "r"(a[0]), "r"(a[1]), "r"(a[2]), "r"(a[3]), "r"(b[0]), "r"(b[1]));
}

// =====================================================================
// split fp32 -> (hi, lo) bf16
// =====================================================================
__global__ void split_kernel(const float* __restrict__ x,
                             __nv_bfloat16* __restrict__ hi,
                             __nv_bfloat16* __restrict__ lo, int n4)
{
    int i = blockIdx.x * blockDim.x + threadIdx.x;
    if (i >= n4) return;
    float4 v = ((const float4*)x)[i];
    __nv_bfloat16 h0 = __float2bfloat16(v.x);
    __nv_bfloat16 h1 = __float2bfloat16(v.y);
    __nv_bfloat16 h2 = __float2bfloat16(v.z);
    __nv_bfloat16 h3 = __float2bfloat16(v.w);
    __nv_bfloat16 l0 = __float2bfloat16(v.x - __bfloat162float(h0));
    __nv_bfloat16 l1 = __float2bfloat16(v.y - __bfloat162float(h1));
    __nv_bfloat16 l2 = __float2bfloat16(v.z - __bfloat162float(h2));
    __nv_bfloat16 l3 = __float2bfloat16(v.w - __bfloat162float(h3));
    __nv_bfloat162* h2p = (__nv_bfloat162*)hi;
    __nv_bfloat162* l2p = (__nv_bfloat162*)lo;
    h2p[2 * i]     = __halves2bfloat162(h0, h1);
    h2p[2 * i + 1] = __halves2bfloat162(h2, h3);
    l2p[2 * i]     = __halves2bfloat162(l0, l1);
    l2p[2 * i + 1] = __halves2bfloat162(l2, l3);
}

// =====================================================================
// RoPE + scale + bf16 split:  fp32 in -> (hi,lo) bf16 out
// =====================================================================
__global__ void rope_split_kernel(const float* __restrict__ buf,
                                  const float* __restrict__ cosb,
                                  const float* __restrict__ sinb,
                                  __nv_bfloat16* __restrict__ oh,
                                  __nv_bfloat16* __restrict__ ol,
                                  int nheads, float scale)
{
    int idx = blockIdx.x * blockDim.x + threadIdx.x;
    int total = 4096 * nheads * 128;
    if (idx >= total) return;
    int j = idx & 127;
    int h = (idx >> 7) % nheads;
    int n = idx / (128 * nheads);
    int t = n & (S_LEN - 1);
    size_t base = (size_t)n * (nheads * 256) + h * 256 + j;
    float x1 = buf[base];
    float x2 = buf[base + 128];
    float c = cosb[t * 128 + j];
    float s = sinb[t * 128 + j];
    float y1 = (x1 * c - x2 * s) * scale;
    float y2 = (x1 * s + x2 * c) * scale;
    __nv_bfloat16 h1 = __float2bfloat16(y1);
    __nv_bfloat16 h2v = __float2bfloat16(y2);
    oh[base]       = h1;
    oh[base + 128] = h2v;
    ol[base]       = __float2bfloat16(y1 - __bfloat162float(h1));
    ol[base + 128] = __float2bfloat16(y2 - __bfloat162float(h2v));
}

// =====================================================================
// HMMA GEMM (unchanged, validated R4)
// =====================================================================
#define STAGES 3
#define TILE_B 10240
#define STAGE_B (4 * TILE_B)
#define GEMM_SMEM (STAGES * STAGE_B)

__device__ __forceinline__ void issue_stage(
    uint32_t sb, int c, int tid, int m0, int n0, int K,
    const __nv_bfloat16* Ah, const __nv_bfloat16* Al,
    const __nv_bfloat16* Bh, const __nv_bfloat16* Bl)
{
    uint32_t st = sb + (uint32_t)(c % STAGES) * STAGE_B;
    int k0 = c * 32;
#pragma unroll
    for (int half = 0; half < 2; half++) {
        int idx = tid + half * 256;
        int row = idx >> 2;
        int seg = idx & 3;
        uint32_t so = (uint32_t)(row * 80 + seg * 16);
        size_t ga = (size_t)(m0 + row) * K + k0 + seg * 8;
        size_t gb = (size_t)(n0 + row) * K + k0 + seg * 8;
        cp_async16(st + so,              Ah + ga);
        cp_async16(st + TILE_B + so,     Al + ga);
        cp_async16(st + 2 * TILE_B + so, Bh + gb);
        cp_async16(st + 3 * TILE_B + so, Bl + gb);
    }
    CP_COMMIT();
}

__global__ __launch_bounds__(256, 1) void gemm_hmma(
    const __nv_bfloat16* __restrict__ Ah, const __nv_bfloat16* __restrict__ Al,
    const __nv_bfloat16* __restrict__ Bh, const __nv_bfloat16* __restrict__ Bl,
    float* __restrict__ C, int M, int N, int K)
{
    extern __shared__ __align__(128) char smem[];
    const uint32_t sb = smem_u32(smem);
    const int tid = threadIdx.x;
    const int wid = tid >> 5, lane = tid & 31;
    const int wm = wid >> 2, wn = wid & 3;
    const int m0 = blockIdx.y * 128, n0 = blockIdx.x * 128;

    float acc[4][4][4];
#pragma unroll
    for (int mi = 0; mi < 4; mi++)
#pragma unroll
        for (int ni = 0; ni < 4; ni++)
#pragma unroll
            for (int r = 0; r < 4; r++) acc[mi][ni][r] = 0.f;

    const int NC = K >> 5;
    issue_stage(sb, 0, tid, m0, n0, K, Ah, Al, Bh, Bl);
    issue_stage(sb, 1, tid, m0, n0, K, Ah, Al, Bh, Bl);

    const uint32_t aoff = (uint32_t)((wm * 64 + (lane & 15)) * 80 +
                                     (lane >> 4) * 16);
    const uint32_t boff = (uint32_t)((wn * 32 + (lane & 7)) * 80 +
                                     ((lane >> 3) & 1) * 16);

    for (int c = 0; c < NC; c++) {
        CP_WAIT1();
        __syncthreads();
        const uint32_t st = sb + (uint32_t)(c % STAGES) * STAGE_B;
        const uint32_t aA = st + aoff;
        const uint32_t aB = st + 2 * TILE_B + boff;

#pragma unroll
        for (int ks = 0; ks < 2; ks++) {
            uint32_t ah[4][4], al[4][4], bh[4][2], bl[4][2];
#pragma unroll
            for (int mi = 0; mi < 4; mi++)
                ldsm_x4(ah[mi], aA + mi * (16 * 80) + ks * 32);
#pragma unroll
            for (int ni = 0; ni < 4; ni++) {
                ldsm_x2(bh[ni], aB + ni * (8 * 80) + ks * 32);
                ldsm_x2(bl[ni], aB + TILE_B + ni * (8 * 80) + ks * 32);
            }
#pragma unroll
            for (int mi = 0; mi < 4; mi++)
#pragma unroll
                for (int ni = 0; ni < 4; ni++) {
                    mma16816(acc[mi][ni], ah[mi], bh[ni]);
                    mma16816(acc[mi][ni], ah[mi], bl[ni]);
                }
#pragma unroll
            for (int mi = 0; mi < 4; mi++)
                ldsm_x4(al[mi], aA + TILE_B + mi * (16 * 80) + ks * 32);
#pragma unroll
            for (int mi = 0; mi < 4; mi++)
#pragma unroll
                for (int ni = 0; ni < 4; ni++)
                    mma16816(acc[mi][ni], al[mi], bh[ni]);
        }
        __syncthreads();
        if (c + 2 < NC)
            issue_stage(sb, c + 2, tid, m0, n0, K, Ah, Al, Bh, Bl);
    }

    const int gr = lane >> 2, cn = lane & 3;
#pragma unroll
    for (int mi = 0; mi < 4; mi++) {
        int r = m0 + wm * 64 + mi * 16 + gr;
#pragma unroll
        for (int ni = 0; ni < 4; ni++) {
            int col = n0 + wn * 32 + ni * 8 + cn * 2;
            *(float2*)(C + (size_t)r * N + col) =
                make_float2(acc[mi][ni][0], acc[mi][ni][1]);
            *(float2*)(C + (size_t)(r + 8) * N + col) =
                make_float2(acc[mi][ni][2], acc[mi][ni][3]);
        }
    }
}

// =====================================================================
// HMMA attention. Block = (b, h, 64 q-rows), 8 warps (4 m x 2 n).
// S = Q K^T (3-product split HMMA), exact fp32 softcap/exp epilogue,
// P split to bf16 hi/lo, O += P~ V (3-product split HMMA).
// =====================================================================
#define DP 528                      // 256 bf16 row + 16B pad
#define PP 144                      // 64 bf16 row + 16B pad
#define SM_QH 0
#define SM_QL (64 * DP)
#define SM_KH (2 * 64 * DP)
#define SM_KL (3 * 64 * DP)
#define SM_VH (4 * 64 * DP)
#define SM_VL (5 * 64 * DP)
#define SM_PH (6 * 64 * DP)
#define SM_PL (SM_PH + 64 * PP)
#define SM_LS (SM_PL + 64 * PP)
#define ATT_SMEM (SM_LS + 256)      // 221440 bytes

__device__ __forceinline__ float capexp(float s, int ig, int jg) {
    float x = s * INV_CAP;
    x = fminf(fmaxf(x, -15.f), 15.f);
    float e = __expf(2.f * x);
    float t = (e - 1.f) / (e + 1.f) * CAP;
    bool win = (jg <= ig) && (ig - jg < 1024);
    return win ? __expf(t - CAP) : 0.f;
}

__global__ __launch_bounds__(256, 1) void attn_hmma(
    const __nv_bfloat16* __restrict__ qh, const __nv_bfloat16* __restrict__ ql,
    const __nv_bfloat16* __restrict__ kh, const __nv_bfloat16* __restrict__ kl,
    const __nv_bfloat16* __restrict__ vh, const __nv_bfloat16* __restrict__ vl,
    float* __restrict__ probs, float* __restrict__ attn_out,
    __nv_bfloat16* __restrict__ gath, __nv_bfloat16* __restrict__ gatl,
    float* __restrict__ linv)
{
    extern __shared__ __align__(128) char smem[];
    const uint32_t sb = smem_u32(smem);
    float* smls = (float*)(smem + SM_LS);
    const int tid = threadIdx.x, wid = tid >> 5, lane = tid & 31;
    const int wm = wid >> 1, wn = wid & 1;
    const int gr = lane >> 2, cn = lane & 3;
    const int q0 = blockIdx.x * 64;
    const int h = blockIdx.y, b = blockIdx.z;
    const int hkv = h >> 1, bh = b * NH + h;

    // load Q tile (hi/lo), 64 rows x 512B each
#pragma unroll
    for (int i = 0; i < 8; i++) {
        int seg = tid + i * 256;
        int r = seg >> 5, s = seg & 31;
        size_t g = ((size_t)(b * S_LEN + q0 + r)) * 2048 + h * 256 + s * 8;
        cp_async16(sb + SM_QH + r * DP + s * 16, qh + g);
        cp_async16(sb + SM_QL + r * DP + s * 16, ql + g);
    }
    CP_COMMIT();
    if (tid < 64) smls[tid] = 0.f;

    float acco[16][4];
#pragma unroll
    for (int i = 0; i < 16; i++)
#pragma unroll
        for (int r = 0; r < 4; r++) acco[i][r] = 0.f;

    const int kstart = max(0, q0 - 1024);
    const int qg0 = q0 + wm * 16 + gr;      // row of c0,c1
    const int qg1 = qg0 + 8;                // row of c2,c3

    for (int kt0 = kstart; kt0 <= q0; kt0 += 64) {
        // K tile
#pragma unroll
        for (int i = 0; i < 8; i++) {
            int seg = tid + i * 256;
            int r = seg >> 5, s = seg & 31;
            size_t g = ((size_t)(b * S_LEN + kt0 + r)) * 1024 + hkv * 256 + s * 8;
            cp_async16(sb + SM_KH + r * DP + s * 16, kh + g);
            cp_async16(sb + SM_KL + r * DP + s * 16, kl + g);
        }
        CP_COMMIT();
        CP_WAIT0();
        __syncthreads();

        // V tile (overlaps with S computation)
#pragma unroll
        for (int i = 0; i < 8; i++) {
            int seg = tid + i * 256;
            int r = seg >> 5, s = seg & 31;
            size_t g = ((size_t)(b * S_LEN + kt0 + r)) * 1024 + hkv * 256 + s * 8;
            cp_async16(sb + SM_VH + r * DP + s * 16, vh + g);
            cp_async16(sb + SM_VL + r * DP + s * 16, vl + g);
        }
        CP_COMMIT();

        // ---- S = Q K^T ----
        float sacc[4][4];
#pragma unroll
        for (int ni = 0; ni < 4; ni++)
#pragma unroll
            for (int r = 0; r < 4; r++) sacc[ni][r] = 0.f;

        const uint32_t qa = sb + SM_QH + (wm * 16 + (lane & 15)) * DP +
                            (lane >> 4) * 16;
        const uint32_t kb = sb + SM_KH + (wn * 32 + (lane & 7)) * DP +
                            ((lane >> 3) & 1) * 16;
#pragma unroll 4
        for (int kc = 0; kc < 16; kc++) {
            uint32_t ah[4], al[4], bhf[4][2], blf[4][2];
            ldsm_x4(ah, qa + kc * 32);
            ldsm_x4(al, qa + (SM_QL - SM_QH) + kc * 32);
#pragma unroll
            for (int ni = 0; ni < 4; ni++) {
                ldsm_x2(bhf[ni], kb + ni * (8 * DP) + kc * 32);
                ldsm_x2(blf[ni], kb + (SM_KL - SM_KH) + ni * (8 * DP) + kc * 32);
            }
#pragma unroll
            for (int ni = 0; ni < 4; ni++) {
                mma16816(sacc[ni], ah, bhf[ni]);
                mma16816(sacc[ni], ah, blf[ni]);
                mma16816(sacc[ni], al, bhf[ni]);
            }
        }

        // ---- softcap/exp epilogue, probs write, P split, row sums ----
        float l0 = 0.f, l1 = 0.f;
#pragma unroll
        for (int ni = 0; ni < 4; ni++) {
            int keyb = kt0 + wn * 32 + ni * 8 + cn * 2;
            float p0 = capexp(sacc[ni][0], qg0, keyb);
            float p1 = capexp(sacc[ni][1], qg0, keyb + 1);
            float p2 = capexp(sacc[ni][2], qg1, keyb);
            float p3 = capexp(sacc[ni][3], qg1, keyb + 1);
            l0 += p0 + p1;
            l1 += p2 + p3;
            *(float2*)(probs + ((size_t)bh * S_LEN + qg0) * S_LEN + keyb) =
                make_float2(p0, p1);
            *(float2*)(probs + ((size_t)bh * S_LEN + qg1) * S_LEN + keyb) =
                make_float2(p2, p3);
            // bf16 hi/lo split of P into smem
            __nv_bfloat16 h0 = __float2bfloat16(p0), h1 = __float2bfloat16(p1);
            __nv_bfloat16 h2 = __float2bfloat16(p2), h3 = __float2bfloat16(p3);
            int pcol = (wn * 32 + ni * 8 + cn * 2) * 2;
            int pr0 = (wm * 16 + gr) * PP, pr1 = pr0 + 8 * PP;
            *(__nv_bfloat162*)(smem + SM_PH + pr0 + pcol) = __halves2bfloat162(h0, h1);
            *(__nv_bfloat162*)(smem + SM_PH + pr1 + pcol) = __halves2bfloat162(h2, h3);
            *(__nv_bfloat162*)(smem + SM_PL + pr0 + pcol) = __halves2bfloat162(
                __float2bfloat16(p0 - __bfloat162float(h0)),
                __float2bfloat16(p1 - __bfloat162float(h1)));
            *(__nv_bfloat162*)(smem + SM_PL + pr1 + pcol) = __halves2bfloat162(
                __float2bfloat16(p2 - __bfloat162float(h2)),
                __float2bfloat16(p3 - __bfloat162float(h3)));
        }
        l0 += __shfl_xor_sync(0xffffffffu, l0, 1);
        l0 += __shfl_xor_sync(0xffffffffu, l0, 2);
        l1 += __shfl_xor_sync(0xffffffffu, l1, 1);
        l1 += __shfl_xor_sync(0xffffffffu, l1, 2);
        if (cn == 0) {
            atomicAdd(&smls[wm * 16 + gr], l0);
            atomicAdd(&smls[wm * 16 + gr + 8], l1);
        }

        CP_WAIT0();
        __syncthreads();   // V ready, P visible to all warps

        // ---- O += P~ V ----
        const uint32_t pa = sb + SM_PH + (wm * 16 + (lane & 15)) * PP +
                            (lane >> 4) * 16;
        const uint32_t vb = sb + SM_VH + (lane & 15) * DP +
                            (wn * 128) * 2 + (lane >> 4) * 16;
#pragma unroll
        for (int kk = 0; kk < 4; kk++) {
            uint32_t ph[4], pl[4];
            ldsm_x4(ph, pa + kk * 32);
            ldsm_x4(pl, pa + (SM_PL - SM_PH) + kk * 32);
#pragma unroll
            for (int nj = 0; nj < 8; nj++) {
                uint32_t vbh[4], vbl[4];
                uint32_t va = vb + kk * (16 * DP) + nj * 32;
                ldsm_x4t(vbh, va);
                ldsm_x4t(vbl, va + (SM_VL - SM_VH));
                mma16816(acco[nj * 2], ph, vbh);
                mma16816(acco[nj * 2], ph, vbl);
                mma16816(acco[nj * 2], pl, vbh);
                mma16816(acco[nj * 2 + 1], ph, vbh + 2);
                mma16816(acco[nj * 2 + 1], ph, vbl + 2);
                mma16816(acco[nj * 2 + 1], pl, vbh + 2);
            }
        }
        __syncthreads();   // before K/V/P overwrite next tile
    }

    // ---- final epilogue ----
    if (tid < 64)
        linv[(size_t)bh * S_LEN + q0 + tid] = 1.f / smls[tid];
    float inv0 = 1.f / smls[wm * 16 + gr];
    float inv1 = 1.f / smls[wm * 16 + gr + 8];
#pragma unroll
    for (int ni = 0; ni < 16; ni++) {
        int col = wn * 128 + ni * 8 + cn * 2;
        float o0 = acco[ni][0] * inv0, o1 = acco[ni][1] * inv0;
        float o2 = acco[ni][2] * inv1, o3 = acco[ni][3] * inv1;
        *(float2*)(attn_out + ((size_t)bh * S_LEN + qg0) * 256 + col) =
            make_float2(o0, o1);
        *(float2*)(attn_out + ((size_t)bh * S_LEN + qg1) * 256 + col) =
            make_float2(o2, o3);
        // bf16 split of g_att for the wo GEMM
        size_t ga0 = ((size_t)(b * S_LEN) + qg0) * 2048 + h * 256 + col;
        size_t ga1 = ((size_t)(b * S_LEN) + qg1) * 2048 + h * 256 + col;
        __nv_bfloat16 h0 = __float2bfloat16(o0), h1 = __float2bfloat16(o1);
        __nv_bfloat16 h2 = __float2bfloat16(o2), h3 = __float2bfloat16(o3);
        *(__nv_bfloat162*)(gath + ga0) = __halves2bfloat162(h0, h1);
        *(__nv_bfloat162*)(gath + ga1) = __halves2bfloat162(h2, h3);
        *(__nv_bfloat162*)(gatl + ga0) = __halves2bfloat162(
            __float2bfloat16(o0 - __bfloat162float(h0)),
            __float2bfloat16(o1 - __bfloat162float(h1)));
        *(__nv_bfloat162*)(gatl + ga1) = __halves2bfloat162(
            __float2bfloat16(o2 - __bfloat162float(h2)),
            __float2bfloat16(o3 - __bfloat162float(h3)));
    }
}

// =====================================================================
// Normalize the banded window region of probs by 1/l.
// =====================================================================
__global__ void norm_probs_kernel(float* __restrict__ probs,
                                  const float* __restrict__ linv)
{
    int row = blockIdx.x;
    int i = row & (S_LEN - 1);
    float inv = linv[row];
    float4* p = (float4*)(probs + (size_t)row * S_LEN);
    int c0 = max(0, i - 1023) >> 2;
    for (int c = c0 + (int)threadIdx.x; (c << 2) <= i; c += blockDim.x) {
        float4 v = p[c];
        v.x *= inv; v.y *= inv; v.z *= inv; v.w *= inv;
        p[c] = v;
    }
}

// =====================================================================
// Outputs: out[2,2048,2048] @0 | probs @8388608 | attn @75497472
// =====================================================================
extern "C" void kernel_launch(void* const* d_in, const int* in_sizes, int n_in,
                              void* d_out, int out_size)
{
    const float* hs = (const float*)d_in[0];
    const float* fc = (const float*)d_in[1];
    const float* fs = (const float*)d_in[2];
    const float* wq = (const float*)d_in[4];
    const float* wk = (const float*)d_in[5];
    const float* wv = (const float*)d_in[6];
    const float* wo = (const float*)d_in[7];

    float* out   = (float*)d_out;
    float* probs = out + 8388608ull;
    float* attn  = probs + 67108864ull;

    float *gq, *gk, *gv, *glinv;
    cudaGetSymbolAddress((void**)&gq, g_q);
    cudaGetSymbolAddress((void**)&gk, g_k);
    cudaGetSymbolAddress((void**)&gv, g_v);
    cudaGetSymbolAddress((void**)&glinv, g_linv);

    void *hsh, *hsl, *atth, *attl, *wqh, *wql, *wkh, *wkl, *wvh, *wvl, *woh, *wol;
    void *qh, *ql, *kh, *kl, *vh, *vl;
    cudaGetSymbolAddress(&hsh, g_hs_h);  cudaGetSymbolAddress(&hsl, g_hs_l);
    cudaGetSymbolAddress(&atth, g_att_h); cudaGetSymbolAddress(&attl, g_att_l);
    cudaGetSymbolAddress(&wqh, g_wq_h);  cudaGetSymbolAddress(&wql, g_wq_l);
    cudaGetSymbolAddress(&wkh, g_wk_h);  cudaGetSymbolAddress(&wkl, g_wk_l);
    cudaGetSymbolAddress(&wvh, g_wv_h);  cudaGetSymbolAddress(&wvl, g_wv_l);
    cudaGetSymbolAddress(&woh, g_wo_h);  cudaGetSymbolAddress(&wol, g_wo_l);
    cudaGetSymbolAddress(&qh, g_qh);     cudaGetSymbolAddress(&ql, g_ql);
    cudaGetSymbolAddress(&kh, g_kh);     cudaGetSymbolAddress(&kl, g_kl);
    cudaGetSymbolAddress(&vh, g_vh);     cudaGetSymbolAddress(&vl, g_vl);

    cudaFuncSetAttribute(gemm_hmma,
                         cudaFuncAttributeMaxDynamicSharedMemorySize, GEMM_SMEM);
    cudaFuncSetAttribute(attn_hmma,
                         cudaFuncAttributeMaxDynamicSharedMemorySize, ATT_SMEM);

    // splits: hs + weights
    split_kernel<<<8192, 256>>>(hs, (__nv_bfloat16*)hsh, (__nv_bfloat16*)hsl, 2097152);
    split_kernel<<<4096, 256>>>(wq, (__nv_bfloat16*)wqh, (__nv_bfloat16*)wql, 1048576);
    split_kernel<<<2048, 256>>>(wk, (__nv_bfloat16*)wkh, (__nv_bfloat16*)wkl, 524288);
    split_kernel<<<2048, 256>>>(wv, (__nv_bfloat16*)wvh, (__nv_bfloat16*)wvl, 524288);
    split_kernel<<<4096, 256>>>(wo, (__nv_bfloat16*)woh, (__nv_bfloat16*)wol, 1048576);

    // QKV projections (HMMA)
    gemm_hmma<<<dim3(16, 32), 256, GEMM_SMEM>>>(
        (const __nv_bfloat16*)hsh, (const __nv_bfloat16*)hsl,
        (const __nv_bfloat16*)wqh, (const __nv_bfloat16*)wql, gq, 4096, 2048, 2048);
    gemm_hmma<<<dim3(8, 32), 256, GEMM_SMEM>>>(
        (const __nv_bfloat16*)hsh, (const __nv_bfloat16*)hsl,
        (const __nv_bfloat16*)wkh, (const __nv_bfloat16*)wkl, gk, 4096, 1024, 2048);
    gemm_hmma<<<dim3(8, 32), 256, GEMM_SMEM>>>(
        (const __nv_bfloat16*)hsh, (const __nv_bfloat16*)hsl,
        (const __nv_bfloat16*)wvh, (const __nv_bfloat16*)wvl, gv, 4096, 1024, 2048);

    // RoPE + scale + split (q scaled by D^-1/2), and V split
    rope_split_kernel<<<16384, 256>>>(gq, fc, fs, (__nv_bfloat16*)qh,
                                      (__nv_bfloat16*)ql, 8, QSCALE);
    rope_split_kernel<<<8192, 256>>>(gk, fc, fs, (__nv_bfloat16*)kh,
                                     (__nv_bfloat16*)kl, 4, 1.0f);
    split_kernel<<<4096, 256>>>(gv, (__nv_bfloat16*)vh, (__nv_bfloat16*)vl, 1048576);

    // attention (HMMA)
    cudaMemsetAsync(probs, 0, 67108864ull * sizeof(float));
    attn_hmma<<<dim3(32, 8, 2), 256, ATT_SMEM>>>(
        (const __nv_bfloat16*)qh, (const __nv_bfloat16*)ql,
        (const __nv_bfloat16*)kh, (const __nv_bfloat16*)kl,
        (const __nv_bfloat16*)vh, (const __nv_bfloat16*)vl,
        probs, attn, (__nv_bfloat16*)atth, (__nv_bfloat16*)attl, glinv);
    norm_probs_kernel<<<32768, 256>>>(probs, glinv);

    // output projection (HMMA)
    gemm_hmma<<<dim3(16, 32), 256, GEMM_SMEM>>>(
        (const __nv_bfloat16*)atth, (const __nv_bfloat16*)attl,
        (const __nv_bfloat16*)woh, (const __nv_bfloat16*)wol, out, 4096, 2048, 2048);
}

// round 6
// speedup vs baseline: 2.6992x; 1.1844x over previous
#include <cuda_runtime.h>
#include <cuda_bf16.h>
#include <math.h>
#include <stdint.h>

#define S_LEN 2048
#define HID   2048
#define NH    8
#define NKV   4
#define HD    256
#define QSCALE 0.0625f       // D^-0.5
#define INV_CAP 0.02f        // 1/50
#define CAP    50.0f

// ---- fp32 scratch ----
__device__ float g_q[(size_t)4096 * 2048];
__device__ float g_k[(size_t)4096 * 1024];
__device__ float g_v[(size_t)4096 * 1024];
__device__ float g_linv[32768];

// ---- bf16 split scratch ----
__device__ uint4 g_hs_h[(size_t)4096 * 2048 / 8];
__device__ uint4 g_hs_l[(size_t)4096 * 2048 / 8];
__device__ uint4 g_att_h[(size_t)4096 * 2048 / 8];
__device__ uint4 g_att_l[(size_t)4096 * 2048 / 8];
__device__ uint4 g_wq_h[(size_t)2048 * 2048 / 8];
__device__ uint4 g_wq_l[(size_t)2048 * 2048 / 8];
__device__ uint4 g_wk_h[(size_t)1024 * 2048 / 8];
__device__ uint4 g_wk_l[(size_t)1024 * 2048 / 8];
__device__ uint4 g_wv_h[(size_t)1024 * 2048 / 8];
__device__ uint4 g_wv_l[(size_t)1024 * 2048 / 8];
__device__ uint4 g_wo_h[(size_t)2048 * 2048 / 8];
__device__ uint4 g_wo_l[(size_t)2048 * 2048 / 8];
__device__ uint4 g_qh[(size_t)4096 * 2048 / 8];
__device__ uint4 g_ql[(size_t)4096 * 2048 / 8];
__device__ uint4 g_kh[(size_t)4096 * 1024 / 8];
__device__ uint4 g_kl[(size_t)4096 * 1024 / 8];
__device__ uint4 g_vh[(size_t)4096 * 1024 / 8];
__device__ uint4 g_vl[(size_t)4096 * 1024 / 8];

// =====================================================================
// helpers
// =====================================================================
__device__ __forceinline__ uint32_t smem_u32(const void* p) {
    uint32_t a;
    asm("{ .reg .u64 t; cvta.to.shared.u64 t, %1; cvt.u32.u64 %0, t; }"
        : "=r"(a) : "l"(p));
    return a;
}
__device__ __forceinline__ void cp_async16(uint32_t saddr, const void* gaddr) {
    asm volatile("cp.async.cg.shared.global [%0], [%1], 16;"
                 :: "r"(saddr), "l"(gaddr) : "memory");
}
#define CP_COMMIT() asm volatile("cp.async.commit_group;" ::: "memory")
#define CP_WAIT1()  asm volatile("cp.async.wait_group 1;" ::: "memory")
#define CP_WAIT0()  asm volatile("cp.async.wait_group 0;" ::: "memory")

__device__ __forceinline__ void ldsm_x4(uint32_t* r, uint32_t addr) {
    asm volatile("ldmatrix.sync.aligned.m8n8.x4.shared.b16 {%0,%1,%2,%3}, [%4];"
                 : "=r"(r[0]), "=r"(r[1]), "=r"(r[2]), "=r"(r[3]) : "r"(addr));
}
__device__ __forceinline__ void ldsm_x4t(uint32_t* r, uint32_t addr) {
    asm volatile("ldmatrix.sync.aligned.m8n8.x4.trans.shared.b16 {%0,%1,%2,%3}, [%4];"
                 : "=r"(r[0]), "=r"(r[1]), "=r"(r[2]), "=r"(r[3]) : "r"(addr));
}
__device__ __forceinline__ void ldsm_x2(uint32_t* r, uint32_t addr) {
    asm volatile("ldmatrix.sync.aligned.m8n8.x2.shared.b16 {%0,%1}, [%2];"
                 : "=r"(r[0]), "=r"(r[1]) : "r"(addr));
}
__device__ __forceinline__ void mma16816(float* c, const uint32_t* a,
                                         const uint32_t* b) {
    asm volatile(
        "mma.sync.aligned.m16n8k16.row.col.f32.bf16.bf16.f32 "
        "{%0,%1,%2,%3}, {%4,%5,%6,%7}, {%8,%9}, {%0,%1,%2,%3};"
        : "+f"(c[0]), "+f"(c[1]), "+f"(c[2]), "+f"(c[3])
        : "r"(a[0]), "r"(a[1]), "r"(a[2]), "r"(a[3]), "r"(b[0]), "r"(b[1]));
}

// =====================================================================
// split fp32 -> (hi, lo) bf16
// =====================================================================
__global__ void split_kernel(const float* __restrict__ x,
                             __nv_bfloat16* __restrict__ hi,
                             __nv_bfloat16* __restrict__ lo, int n4)
{
    int i = blockIdx.x * blockDim.x + threadIdx.x;
    if (i >= n4) return;
    float4 v = ((const float4*)x)[i];
    __nv_bfloat16 h0 = __float2bfloat16(v.x);
    __nv_bfloat16 h1 = __float2bfloat16(v.y);
    __nv_bfloat16 h2 = __float2bfloat16(v.z);
    __nv_bfloat16 h3 = __float2bfloat16(v.w);
    __nv_bfloat16 l0 = __float2bfloat16(v.x - __bfloat162float(h0));
    __nv_bfloat16 l1 = __float2bfloat16(v.y - __bfloat162float(h1));
    __nv_bfloat16 l2 = __float2bfloat16(v.z - __bfloat162float(h2));
    __nv_bfloat16 l3 = __float2bfloat16(v.w - __bfloat162float(h3));
    __nv_bfloat162* h2p = (__nv_bfloat162*)hi;
    __nv_bfloat162* l2p = (__nv_bfloat162*)lo;
    h2p[2 * i]     = __halves2bfloat162(h0, h1);
    h2p[2 * i + 1] = __halves2bfloat162(h2, h3);
    l2p[2 * i]     = __halves2bfloat162(l0, l1);
    l2p[2 * i + 1] = __halves2bfloat162(l2, l3);
}

// =====================================================================
// RoPE + scale + bf16 split
// =====================================================================
__global__ void rope_split_kernel(const float* __restrict__ buf,
                                  const float* __restrict__ cosb,
                                  const float* __restrict__ sinb,
                                  __nv_bfloat16* __restrict__ oh,
                                  __nv_bfloat16* __restrict__ ol,
                                  int nheads, float scale)
{
    int idx = blockIdx.x * blockDim.x + threadIdx.x;
    int total = 4096 * nheads * 128;
    if (idx >= total) return;
    int j = idx & 127;
    int h = (idx >> 7) % nheads;
    int n = idx / (128 * nheads);
    int t = n & (S_LEN - 1);
    size_t base = (size_t)n * (nheads * 256) + h * 256 + j;
    float x1 = buf[base];
    float x2 = buf[base + 128];
    float c = cosb[t * 128 + j];
    float s = sinb[t * 128 + j];
    float y1 = (x1 * c - x2 * s) * scale;
    float y2 = (x1 * s + x2 * c) * scale;
    __nv_bfloat16 h1 = __float2bfloat16(y1);
    __nv_bfloat16 h2v = __float2bfloat16(y2);
    oh[base]       = h1;
    oh[base + 128] = h2v;
    ol[base]       = __float2bfloat16(y1 - __bfloat162float(h1));
    ol[base + 128] = __float2bfloat16(y2 - __bfloat162float(h2v));
}

// =====================================================================
// HMMA GEMM: 2-stage pipeline, 80KB smem, 2 CTAs/SM.
// =====================================================================
#define STAGES 2
#define TILE_B 10240
#define STAGE_B (4 * TILE_B)
#define GEMM_SMEM (STAGES * STAGE_B)   // 81920

__device__ __forceinline__ void issue_stage(
    uint32_t sb, int c, int tid, int m0, int n0, int K,
    const __nv_bfloat16* Ah, const __nv_bfloat16* Al,
    const __nv_bfloat16* Bh, const __nv_bfloat16* Bl)
{
    uint32_t st = sb + (uint32_t)(c & 1) * STAGE_B;
    int k0 = c * 32;
#pragma unroll
    for (int half = 0; half < 2; half++) {
        int idx = tid + half * 256;
        int row = idx >> 2;
        int seg = idx & 3;
        uint32_t so = (uint32_t)(row * 80 + seg * 16);
        size_t ga = (size_t)(m0 + row) * K + k0 + seg * 8;
        size_t gb = (size_t)(n0 + row) * K + k0 + seg * 8;
        cp_async16(st + so,              Ah + ga);
        cp_async16(st + TILE_B + so,     Al + ga);
        cp_async16(st + 2 * TILE_B + so, Bh + gb);
        cp_async16(st + 3 * TILE_B + so, Bl + gb);
    }
    CP_COMMIT();
}

__global__ __launch_bounds__(256, 2) void gemm_hmma(
    const __nv_bfloat16* __restrict__ Ah, const __nv_bfloat16* __restrict__ Al,
    const __nv_bfloat16* __restrict__ Bh, const __nv_bfloat16* __restrict__ Bl,
    float* __restrict__ C, int M, int N, int K)
{
    extern __shared__ __align__(128) char smem[];
    const uint32_t sb = smem_u32(smem);
    const int tid = threadIdx.x;
    const int wid = tid >> 5, lane = tid & 31;
    const int wm = wid >> 2, wn = wid & 3;
    const int m0 = blockIdx.y * 128, n0 = blockIdx.x * 128;

    float acc[4][4][4];
#pragma unroll
    for (int mi = 0; mi < 4; mi++)
#pragma unroll
        for (int ni = 0; ni < 4; ni++)
#pragma unroll
            for (int r = 0; r < 4; r++) acc[mi][ni][r] = 0.f;

    const int NC = K >> 5;
    issue_stage(sb, 0, tid, m0, n0, K, Ah, Al, Bh, Bl);

    const uint32_t aoff = (uint32_t)((wm * 64 + (lane & 15)) * 80 +
                                     (lane >> 4) * 16);
    const uint32_t boff = (uint32_t)((wn * 32 + (lane & 7)) * 80 +
                                     ((lane >> 3) & 1) * 16);

    for (int c = 0; c < NC; c++) {
        // issue next stage first: its buffer was released by the trailing
        // __syncthreads of iteration c-1; keeps one load in flight under compute
        if (c + 1 < NC)
            issue_stage(sb, c + 1, tid, m0, n0, K, Ah, Al, Bh, Bl);
        if (c + 1 < NC) CP_WAIT1(); else CP_WAIT0();
        __syncthreads();
        const uint32_t st = sb + (uint32_t)(c & 1) * STAGE_B;
        const uint32_t aA = st + aoff;
        const uint32_t aB = st + 2 * TILE_B + boff;

#pragma unroll
        for (int ks = 0; ks < 2; ks++) {
            uint32_t ah[4][4], al[4][4], bh[4][2], bl[4][2];
#pragma unroll
            for (int mi = 0; mi < 4; mi++)
                ldsm_x4(ah[mi], aA + mi * (16 * 80) + ks * 32);
#pragma unroll
            for (int ni = 0; ni < 4; ni++) {
                ldsm_x2(bh[ni], aB + ni * (8 * 80) + ks * 32);
                ldsm_x2(bl[ni], aB + TILE_B + ni * (8 * 80) + ks * 32);
            }
#pragma unroll
            for (int mi = 0; mi < 4; mi++)
#pragma unroll
                for (int ni = 0; ni < 4; ni++) {
                    mma16816(acc[mi][ni], ah[mi], bh[ni]);
                    mma16816(acc[mi][ni], ah[mi], bl[ni]);
                }
#pragma unroll
            for (int mi = 0; mi < 4; mi++)
                ldsm_x4(al[mi], aA + TILE_B + mi * (16 * 80) + ks * 32);
#pragma unroll
            for (int mi = 0; mi < 4; mi++)
#pragma unroll
                for (int ni = 0; ni < 4; ni++)
                    mma16816(acc[mi][ni], al[mi], bh[ni]);
        }
        __syncthreads();
    }

    const int gr = lane >> 2, cn = lane & 3;
#pragma unroll
    for (int mi = 0; mi < 4; mi++) {
        int r = m0 + wm * 64 + mi * 16 + gr;
#pragma unroll
        for (int ni = 0; ni < 4; ni++) {
            int col = n0 + wn * 32 + ni * 8 + cn * 2;
            *(float2*)(C + (size_t)r * N + col) =
                make_float2(acc[mi][ni][0], acc[mi][ni][1]);
            *(float2*)(C + (size_t)(r + 8) * N + col) =
                make_float2(acc[mi][ni][2], acc[mi][ni][3]);
        }
    }
}

// =====================================================================
// HMMA attention (validated R5) + coalesced probs writeback from smem P.
// =====================================================================
#define DP 528
#define PP 144
#define SM_QH 0
#define SM_QL (64 * DP)
#define SM_KH (2 * 64 * DP)
#define SM_KL (3 * 64 * DP)
#define SM_VH (4 * 64 * DP)
#define SM_VL (5 * 64 * DP)
#define SM_PH (6 * 64 * DP)
#define SM_PL (SM_PH + 64 * PP)
#define SM_LS (SM_PL + 64 * PP)
#define ATT_SMEM (SM_LS + 256)

__device__ __forceinline__ float capexp(float s, int ig, int jg) {
    float x = s * INV_CAP;
    x = fminf(fmaxf(x, -15.f), 15.f);
    float e = __expf(2.f * x);
    float t = (e - 1.f) / (e + 1.f) * CAP;
    bool win = (jg <= ig) && (ig - jg < 1024);
    return win ? __expf(t - CAP) : 0.f;
}

__global__ __launch_bounds__(256, 1) void attn_hmma(
    const __nv_bfloat16* __restrict__ qh, const __nv_bfloat16* __restrict__ ql,
    const __nv_bfloat16* __restrict__ kh, const __nv_bfloat16* __restrict__ kl,
    const __nv_bfloat16* __restrict__ vh, const __nv_bfloat16* __restrict__ vl,
    float* __restrict__ probs, float* __restrict__ attn_out,
    __nv_bfloat16* __restrict__ gath, __nv_bfloat16* __restrict__ gatl,
    float* __restrict__ linv)
{
    extern __shared__ __align__(128) char smem[];
    const uint32_t sb = smem_u32(smem);
    float* smls = (float*)(smem + SM_LS);
    const int tid = threadIdx.x, wid = tid >> 5, lane = tid & 31;
    const int wm = wid >> 1, wn = wid & 1;
    const int gr = lane >> 2, cn = lane & 3;
    const int q0 = blockIdx.x * 64;
    const int h = blockIdx.y, b = blockIdx.z;
    const int hkv = h >> 1, bh = b * NH + h;

#pragma unroll
    for (int i = 0; i < 8; i++) {
        int seg = tid + i * 256;
        int r = seg >> 5, s = seg & 31;
        size_t g = ((size_t)(b * S_LEN + q0 + r)) * 2048 + h * 256 + s * 8;
        cp_async16(sb + SM_QH + r * DP + s * 16, qh + g);
        cp_async16(sb + SM_QL + r * DP + s * 16, ql + g);
    }
    CP_COMMIT();
    if (tid < 64) smls[tid] = 0.f;

    float acco[16][4];
#pragma unroll
    for (int i = 0; i < 16; i++)
#pragma unroll
        for (int r = 0; r < 4; r++) acco[i][r] = 0.f;

    const int kstart = max(0, q0 - 1024);
    const int qg0 = q0 + wm * 16 + gr;
    const int qg1 = qg0 + 8;

    for (int kt0 = kstart; kt0 <= q0; kt0 += 64) {
#pragma unroll
        for (int i = 0; i < 8; i++) {
            int seg = tid + i * 256;
            int r = seg >> 5, s = seg & 31;
            size_t g = ((size_t)(b * S_LEN + kt0 + r)) * 1024 + hkv * 256 + s * 8;
            cp_async16(sb + SM_KH + r * DP + s * 16, kh + g);
            cp_async16(sb + SM_KL + r * DP + s * 16, kl + g);
        }
        CP_COMMIT();
        CP_WAIT0();
        __syncthreads();

#pragma unroll
        for (int i = 0; i < 8; i++) {
            int seg = tid + i * 256;
            int r = seg >> 5, s = seg & 31;
            size_t g = ((size_t)(b * S_LEN + kt0 + r)) * 1024 + hkv * 256 + s * 8;
            cp_async16(sb + SM_VH + r * DP + s * 16, vh + g);
            cp_async16(sb + SM_VL + r * DP + s * 16, vl + g);
        }
        CP_COMMIT();

        // ---- S = Q K^T ----
        float sacc[4][4];
#pragma unroll
        for (int ni = 0; ni < 4; ni++)
#pragma unroll
            for (int r = 0; r < 4; r++) sacc[ni][r] = 0.f;

        const uint32_t qa = sb + SM_QH + (wm * 16 + (lane & 15)) * DP +
                            (lane >> 4) * 16;
        const uint32_t kb = sb + SM_KH + (wn * 32 + (lane & 7)) * DP +
                            ((lane >> 3) & 1) * 16;
#pragma unroll 4
        for (int kc = 0; kc < 16; kc++) {
            uint32_t ah[4], al[4], bhf[4][2], blf[4][2];
            ldsm_x4(ah, qa + kc * 32);
            ldsm_x4(al, qa + (SM_QL - SM_QH) + kc * 32);
#pragma unroll
            for (int ni = 0; ni < 4; ni++) {
                ldsm_x2(bhf[ni], kb + ni * (8 * DP) + kc * 32);
                ldsm_x2(blf[ni], kb + (SM_KL - SM_KH) + ni * (8 * DP) + kc * 32);
            }
#pragma unroll
            for (int ni = 0; ni < 4; ni++) {
                mma16816(sacc[ni], ah, bhf[ni]);
                mma16816(sacc[ni], ah, blf[ni]);
                mma16816(sacc[ni], al, bhf[ni]);
            }
        }

        // ---- softcap/exp, P split into smem, row sums ----
        float l0 = 0.f, l1 = 0.f;
#pragma unroll
        for (int ni = 0; ni < 4; ni++) {
            int keyb = kt0 + wn * 32 + ni * 8 + cn * 2;
            float p0 = capexp(sacc[ni][0], qg0, keyb);
            float p1 = capexp(sacc[ni][1], qg0, keyb + 1);
            float p2 = capexp(sacc[ni][2], qg1, keyb);
            float p3 = capexp(sacc[ni][3], qg1, keyb + 1);
            l0 += p0 + p1;
            l1 += p2 + p3;
            __nv_bfloat16 h0 = __float2bfloat16(p0), h1 = __float2bfloat16(p1);
            __nv_bfloat16 h2 = __float2bfloat16(p2), h3 = __float2bfloat16(p3);
            int pcol = (wn * 32 + ni * 8 + cn * 2) * 2;
            int pr0 = (wm * 16 + gr) * PP, pr1 = pr0 + 8 * PP;
            *(__nv_bfloat162*)(smem + SM_PH + pr0 + pcol) = __halves2bfloat162(h0, h1);
            *(__nv_bfloat162*)(smem + SM_PH + pr1 + pcol) = __halves2bfloat162(h2, h3);
            *(__nv_bfloat162*)(smem + SM_PL + pr0 + pcol) = __halves2bfloat162(
                __float2bfloat16(p0 - __bfloat162float(h0)),
                __float2bfloat16(p1 - __bfloat162float(h1)));
            *(__nv_bfloat162*)(smem + SM_PL + pr1 + pcol) = __halves2bfloat162(
                __float2bfloat16(p2 - __bfloat162float(h2)),
                __float2bfloat16(p3 - __bfloat162float(h3)));
        }
        l0 += __shfl_xor_sync(0xffffffffu, l0, 1);
        l0 += __shfl_xor_sync(0xffffffffu, l0, 2);
        l1 += __shfl_xor_sync(0xffffffffu, l1, 1);
        l1 += __shfl_xor_sync(0xffffffffu, l1, 2);
        if (cn == 0) {
            atomicAdd(&smls[wm * 16 + gr], l0);
            atomicAdd(&smls[wm * 16 + gr + 8], l1);
        }

        CP_WAIT0();
        __syncthreads();   // V ready, P visible

        // ---- coalesced probs writeback from smem P (hi+lo) ----
#pragma unroll
        for (int i = 0; i < 4; i++) {
            int idx = tid + i * 256;
            int r = idx >> 4;
            int c4 = (idx & 15) * 4;      // starting column (of 64)
            uint2 vh2 = *(const uint2*)(smem + SM_PH + r * PP + c4 * 2);
            uint2 vl2 = *(const uint2*)(smem + SM_PL + r * PP + c4 * 2);
            float2 a0 = __bfloat1622float2(*(__nv_bfloat162*)&vh2.x);
            float2 a1 = __bfloat1622float2(*(__nv_bfloat162*)&vh2.y);
            float2 b0 = __bfloat1622float2(*(__nv_bfloat162*)&vl2.x);
            float2 b1 = __bfloat1622float2(*(__nv_bfloat162*)&vl2.y);
            float4 pv;
            pv.x = a0.x + b0.x; pv.y = a0.y + b0.y;
            pv.z = a1.x + b1.x; pv.w = a1.y + b1.y;
            *(float4*)(probs + ((size_t)bh * S_LEN + q0 + r) * S_LEN + kt0 + c4) = pv;
        }

        // ---- O += P~ V ----
        const uint32_t pa = sb + SM_PH + (wm * 16 + (lane & 15)) * PP +
                            (lane >> 4) * 16;
        const uint32_t vb = sb + SM_VH + (lane & 15) * DP +
                            (wn * 128) * 2 + (lane >> 4) * 16;
#pragma unroll
        for (int kk = 0; kk < 4; kk++) {
            uint32_t ph[4], pl[4];
            ldsm_x4(ph, pa + kk * 32);
            ldsm_x4(pl, pa + (SM_PL - SM_PH) + kk * 32);
#pragma unroll
            for (int nj = 0; nj < 8; nj++) {
                uint32_t vbh[4], vbl[4];
                uint32_t va = vb + kk * (16 * DP) + nj * 32;
                ldsm_x4t(vbh, va);
                ldsm_x4t(vbl, va + (SM_VL - SM_VH));
                mma16816(acco[nj * 2], ph, vbh);
                mma16816(acco[nj * 2], ph, vbl);
                mma16816(acco[nj * 2], pl, vbh);
                mma16816(acco[nj * 2 + 1], ph, vbh + 2);
                mma16816(acco[nj * 2 + 1], ph, vbl + 2);
                mma16816(acco[nj * 2 + 1], pl, vbh + 2);
            }
        }
        __syncthreads();
    }

    // ---- final epilogue ----
    if (tid < 64)
        linv[(size_t)bh * S_LEN + q0 + tid] = 1.f / smls[tid];
    float inv0 = 1.f / smls[wm * 16 + gr];
    float inv1 = 1.f / smls[wm * 16 + gr + 8];
#pragma unroll
    for (int ni = 0; ni < 16; ni++) {
        int col = wn * 128 + ni * 8 + cn * 2;
        float o0 = acco[ni][0] * inv0, o1 = acco[ni][1] * inv0;
        float o2 = acco[ni][2] * inv1, o3 = acco[ni][3] * inv1;
        *(float2*)(attn_out + ((size_t)bh * S_LEN + qg0) * 256 + col) =
            make_float2(o0, o1);
        *(float2*)(attn_out + ((size_t)bh * S_LEN + qg1) * 256 + col) =
            make_float2(o2, o3);
        size_t ga0 = ((size_t)(b * S_LEN) + qg0) * 2048 + h * 256 + col;
        size_t ga1 = ((size_t)(b * S_LEN) + qg1) * 2048 + h * 256 + col;
        __nv_bfloat16 h0 = __float2bfloat16(o0), h1 = __float2bfloat16(o1);
        __nv_bfloat16 h2 = __float2bfloat16(o2), h3 = __float2bfloat16(o3);
        *(__nv_bfloat162*)(gath + ga0) = __halves2bfloat162(h0, h1);
        *(__nv_bfloat162*)(gath + ga1) = __halves2bfloat162(h2, h3);
        *(__nv_bfloat162*)(gatl + ga0) = __halves2bfloat162(
            __float2bfloat16(o0 - __bfloat162float(h0)),
            __float2bfloat16(o1 - __bfloat162float(h1)));
        *(__nv_bfloat162*)(gatl + ga1) = __halves2bfloat162(
            __float2bfloat16(o2 - __bfloat162float(h2)),
            __float2bfloat16(o3 - __bfloat162float(h3)));
    }
}

// =====================================================================
// Normalize the banded window region of probs by 1/l.
// =====================================================================
__global__ void norm_probs_kernel(float* __restrict__ probs,
                                  const float* __restrict__ linv)
{
    int row = blockIdx.x;
    int i = row & (S_LEN - 1);
    float inv = linv[row];
    float4* p = (float4*)(probs + (size_t)row * S_LEN);
    int c0 = max(0, i - 1023) >> 2;
    for (int c = c0 + (int)threadIdx.x; (c << 2) <= i; c += blockDim.x) {
        float4 v = p[c];
        v.x *= inv; v.y *= inv; v.z *= inv; v.w *= inv;
        p[c] = v;
    }
}

// =====================================================================
// Outputs: out[2,2048,2048] @0 | probs @8388608 | attn @75497472
// =====================================================================
extern "C" void kernel_launch(void* const* d_in, const int* in_sizes, int n_in,
                              void* d_out, int out_size)
{
    const float* hs = (const float*)d_in[0];
    const float* fc = (const float*)d_in[1];
    const float* fs = (const float*)d_in[2];
    const float* wq = (const float*)d_in[4];
    const float* wk = (const float*)d_in[5];
    const float* wv = (const float*)d_in[6];
    const float* wo = (const float*)d_in[7];

    float* out   = (float*)d_out;
    float* probs = out + 8388608ull;
    float* attn  = probs + 67108864ull;

    float *gq, *gk, *gv, *glinv;
    cudaGetSymbolAddress((void**)&gq, g_q);
    cudaGetSymbolAddress((void**)&gk, g_k);
    cudaGetSymbolAddress((void**)&gv, g_v);
    cudaGetSymbolAddress((void**)&glinv, g_linv);

    void *hsh, *hsl, *atth, *attl, *wqh, *wql, *wkh, *wkl, *wvh, *wvl, *woh, *wol;
    void *qh, *ql, *kh, *kl, *vh, *vl;
    cudaGetSymbolAddress(&hsh, g_hs_h);  cudaGetSymbolAddress(&hsl, g_hs_l);
    cudaGetSymbolAddress(&atth, g_att_h); cudaGetSymbolAddress(&attl, g_att_l);
    cudaGetSymbolAddress(&wqh, g_wq_h);  cudaGetSymbolAddress(&wql, g_wq_l);
    cudaGetSymbolAddress(&wkh, g_wk_h);  cudaGetSymbolAddress(&wkl, g_wk_l);
    cudaGetSymbolAddress(&wvh, g_wv_h);  cudaGetSymbolAddress(&wvl, g_wv_l);
    cudaGetSymbolAddress(&woh, g_wo_h);  cudaGetSymbolAddress(&wol, g_wo_l);
    cudaGetSymbolAddress(&qh, g_qh);     cudaGetSymbolAddress(&ql, g_ql);
    cudaGetSymbolAddress(&kh, g_kh);     cudaGetSymbolAddress(&kl, g_kl);
    cudaGetSymbolAddress(&vh, g_vh);     cudaGetSymbolAddress(&vl, g_vl);

    cudaFuncSetAttribute(gemm_hmma,
                         cudaFuncAttributeMaxDynamicSharedMemorySize, GEMM_SMEM);
    cudaFuncSetAttribute(attn_hmma,
                         cudaFuncAttributeMaxDynamicSharedMemorySize, ATT_SMEM);

    split_kernel<<<8192, 256>>>(hs, (__nv_bfloat16*)hsh, (__nv_bfloat16*)hsl, 2097152);
    split_kernel<<<4096, 256>>>(wq, (__nv_bfloat16*)wqh, (__nv_bfloat16*)wql, 1048576);
    split_kernel<<<2048, 256>>>(wk, (__nv_bfloat16*)wkh, (__nv_bfloat16*)wkl, 524288);
    split_kernel<<<2048, 256>>>(wv, (__nv_bfloat16*)wvh, (__nv_bfloat16*)wvl, 524288);
    split_kernel<<<4096, 256>>>(wo, (__nv_bfloat16*)woh, (__nv_bfloat16*)wol, 1048576);

    gemm_hmma<<<dim3(16, 32), 256, GEMM_SMEM>>>(
        (const __nv_bfloat16*)hsh, (const __nv_bfloat16*)hsl,
        (const __nv_bfloat16*)wqh, (const __nv_bfloat16*)wql, gq, 4096, 2048, 2048);
    gemm_hmma<<<dim3(8, 32), 256, GEMM_SMEM>>>(
        (const __nv_bfloat16*)hsh, (const __nv_bfloat16*)hsl,
        (const __nv_bfloat16*)wkh, (const __nv_bfloat16*)wkl, gk, 4096, 1024, 2048);
    gemm_hmma<<<dim3(8, 32), 256, GEMM_SMEM>>>(
        (const __nv_bfloat16*)hsh, (const __nv_bfloat16*)hsl,
        (const __nv_bfloat16*)wvh, (const __nv_bfloat16*)wvl, gv, 4096, 1024, 2048);

    rope_split_kernel<<<16384, 256>>>(gq, fc, fs, (__nv_bfloat16*)qh,
                                      (__nv_bfloat16*)ql, 8, QSCALE);
    rope_split_kernel<<<8192, 256>>>(gk, fc, fs, (__nv_bfloat16*)kh,
                                     (__nv_bfloat16*)kl, 4, 1.0f);
    split_kernel<<<4096, 256>>>(gv, (__nv_bfloat16*)vh, (__nv_bfloat16*)vl, 1048576);

    cudaMemsetAsync(probs, 0, 67108864ull * sizeof(float));
    attn_hmma<<<dim3(32, 8, 2), 256, ATT_SMEM>>>(
        (const __nv_bfloat16*)qh, (const __nv_bfloat16*)ql,
        (const __nv_bfloat16*)kh, (const __nv_bfloat16*)kl,
        (const __nv_bfloat16*)vh, (const __nv_bfloat16*)vl,
        probs, attn, (__nv_bfloat16*)atth, (__nv_bfloat16*)attl, glinv);
    norm_probs_kernel<<<32768, 256>>>(probs, glinv);

    gemm_hmma<<<dim3(16, 32), 256, GEMM_SMEM>>>(
        (const __nv_bfloat16*)atth, (const __nv_bfloat16*)attl,
        (const __nv_bfloat16*)woh, (const __nv_bfloat16*)wol, out, 4096, 2048, 2048);
}

// round 7
// speedup vs baseline: 2.8665x; 1.0620x over previous
#include <cuda_runtime.h>
#include <cuda_bf16.h>
#include <math.h>
#include <stdint.h>

#define S_LEN 2048
#define HID   2048
#define NH    8
#define NKV   4
#define HD    256
#define QSCALE 0.0625f       // D^-0.5
#define INV_CAP 0.02f        // 1/50
#define CAP    50.0f

// ---- fp32 scratch ----
__device__ float g_qkv[(size_t)4096 * 4096];   // q cols 0-2047 | k 2048-3071 | v 3072-4095
__device__ float g_linv[32768];

// ---- bf16 split scratch ----
__device__ uint4 g_hs_h[(size_t)4096 * 2048 / 8];
__device__ uint4 g_hs_l[(size_t)4096 * 2048 / 8];
__device__ uint4 g_att_h[(size_t)4096 * 2048 / 8];
__device__ uint4 g_att_l[(size_t)4096 * 2048 / 8];
__device__ uint4 g_w_h[(size_t)4096 * 2048 / 8];   // wq rows 0-2047 | wk | wv
__device__ uint4 g_w_l[(size_t)4096 * 2048 / 8];
__device__ uint4 g_wo_h[(size_t)2048 * 2048 / 8];
__device__ uint4 g_wo_l[(size_t)2048 * 2048 / 8];
__device__ uint4 g_qh[(size_t)4096 * 2048 / 8];
__device__ uint4 g_ql[(size_t)4096 * 2048 / 8];
__device__ uint4 g_kh[(size_t)4096 * 1024 / 8];
__device__ uint4 g_kl[(size_t)4096 * 1024 / 8];
__device__ uint4 g_vh[(size_t)4096 * 1024 / 8];
__device__ uint4 g_vl[(size_t)4096 * 1024 / 8];

// =====================================================================
// helpers
// =====================================================================
__device__ __forceinline__ uint32_t smem_u32(const void* p) {
    uint32_t a;
    asm("{ .reg .u64 t; cvta.to.shared.u64 t, %1; cvt.u32.u64 %0, t; }"
        : "=r"(a) : "l"(p));
    return a;
}
__device__ __forceinline__ void cp_async16(uint32_t saddr, const void* gaddr) {
    asm volatile("cp.async.cg.shared.global [%0], [%1], 16;"
                 :: "r"(saddr), "l"(gaddr) : "memory");
}
#define CP_COMMIT() asm volatile("cp.async.commit_group;" ::: "memory")
#define CP_WAIT1()  asm volatile("cp.async.wait_group 1;" ::: "memory")
#define CP_WAIT0()  asm volatile("cp.async.wait_group 0;" ::: "memory")

__device__ __forceinline__ void ldsm_x4(uint32_t* r, uint32_t addr) {
    asm volatile("ldmatrix.sync.aligned.m8n8.x4.shared.b16 {%0,%1,%2,%3}, [%4];"
                 : "=r"(r[0]), "=r"(r[1]), "=r"(r[2]), "=r"(r[3]) : "r"(addr));
}
__device__ __forceinline__ void ldsm_x4t(uint32_t* r, uint32_t addr) {
    asm volatile("ldmatrix.sync.aligned.m8n8.x4.trans.shared.b16 {%0,%1,%2,%3}, [%4];"
                 : "=r"(r[0]), "=r"(r[1]), "=r"(r[2]), "=r"(r[3]) : "r"(addr));
}
__device__ __forceinline__ void ldsm_x2(uint32_t* r, uint32_t addr) {
    asm volatile("ldmatrix.sync.aligned.m8n8.x2.shared.b16 {%0,%1}, [%2];"
                 : "=r"(r[0]), "=r"(r[1]) : "r"(addr));
}
__device__ __forceinline__ void mma16816(float* c, const uint32_t* a,
                                         const uint32_t* b) {
    asm volatile(
        "mma.sync.aligned.m16n8k16.row.col.f32.bf16.bf16.f32 "
        "{%0,%1,%2,%3}, {%4,%5,%6,%7}, {%8,%9}, {%0,%1,%2,%3};"
        : "+f"(c[0]), "+f"(c[1]), "+f"(c[2]), "+f"(c[3])
        : "r"(a[0]), "r"(a[1]), "r"(a[2]), "r"(a[3]), "r"(b[0]), "r"(b[1]));
}

// =====================================================================
// split fp32 -> (hi, lo) bf16  (contiguous)
// =====================================================================
__global__ void split_kernel(const float* __restrict__ x,
                             __nv_bfloat16* __restrict__ hi,
                             __nv_bfloat16* __restrict__ lo, int n4)
{
    int i = blockIdx.x * blockDim.x + threadIdx.x;
    if (i >= n4) return;
    float4 v = ((const float4*)x)[i];
    __nv_bfloat16 h0 = __float2bfloat16(v.x);
    __nv_bfloat16 h1 = __float2bfloat16(v.y);
    __nv_bfloat16 h2 = __float2bfloat16(v.z);
    __nv_bfloat16 h3 = __float2bfloat16(v.w);
    __nv_bfloat16 l0 = __float2bfloat16(v.x - __bfloat162float(h0));
    __nv_bfloat16 l1 = __float2bfloat16(v.y - __bfloat162float(h1));
    __nv_bfloat16 l2 = __float2bfloat16(v.z - __bfloat162float(h2));
    __nv_bfloat16 l3 = __float2bfloat16(v.w - __bfloat162float(h3));
    __nv_bfloat162* h2p = (__nv_bfloat162*)hi;
    __nv_bfloat162* l2p = (__nv_bfloat162*)lo;
    h2p[2 * i]     = __halves2bfloat162(h0, h1);
    h2p[2 * i + 1] = __halves2bfloat162(h2, h3);
    l2p[2 * i]     = __halves2bfloat162(l0, l1);
    l2p[2 * i + 1] = __halves2bfloat162(l2, l3);
}

// =====================================================================
// split fp32 submatrix (row stride 4096, col offset) -> bf16 hi/lo [., 1024]
// =====================================================================
__global__ void split_strided_kernel(const float* __restrict__ x, int coloff,
                                     __nv_bfloat16* __restrict__ hi,
                                     __nv_bfloat16* __restrict__ lo)
{
    int i = blockIdx.x * blockDim.x + threadIdx.x;   // over 4096*256 float4s
    if (i >= 4096 * 256) return;
    int row = i >> 8, c4 = (i & 255) << 2;
    float4 v = *(const float4*)(x + (size_t)row * 4096 + coloff + c4);
    __nv_bfloat16 h0 = __float2bfloat16(v.x);
    __nv_bfloat16 h1 = __float2bfloat16(v.y);
    __nv_bfloat16 h2 = __float2bfloat16(v.z);
    __nv_bfloat16 h3 = __float2bfloat16(v.w);
    size_t o = (size_t)row * 1024 + c4;
    *(__nv_bfloat162*)(hi + o)     = __halves2bfloat162(h0, h1);
    *(__nv_bfloat162*)(hi + o + 2) = __halves2bfloat162(h2, h3);
    *(__nv_bfloat162*)(lo + o)     = __halves2bfloat162(
        __float2bfloat16(v.x - __bfloat162float(h0)),
        __float2bfloat16(v.y - __bfloat162float(h1)));
    *(__nv_bfloat162*)(lo + o + 2) = __halves2bfloat162(
        __float2bfloat16(v.z - __bfloat162float(h2)),
        __float2bfloat16(v.w - __bfloat162float(h3)));
}

// =====================================================================
// RoPE + scale + bf16 split; input row stride 4096 with column offset
// =====================================================================
__global__ void rope_split_kernel(const float* __restrict__ buf, int coloff,
                                  const float* __restrict__ cosb,
                                  const float* __restrict__ sinb,
                                  __nv_bfloat16* __restrict__ oh,
                                  __nv_bfloat16* __restrict__ ol,
                                  int nheads, float scale)
{
    int idx = blockIdx.x * blockDim.x + threadIdx.x;
    int total = 4096 * nheads * 128;
    if (idx >= total) return;
    int j = idx & 127;
    int h = (idx >> 7) % nheads;
    int n = idx / (128 * nheads);
    int t = n & (S_LEN - 1);
    size_t ibase = (size_t)n * 4096 + coloff + h * 256 + j;
    size_t obase = (size_t)n * (nheads * 256) + h * 256 + j;
    float x1 = buf[ibase];
    float x2 = buf[ibase + 128];
    float c = cosb[t * 128 + j];
    float s = sinb[t * 128 + j];
    float y1 = (x1 * c - x2 * s) * scale;
    float y2 = (x1 * s + x2 * c) * scale;
    __nv_bfloat16 h1 = __float2bfloat16(y1);
    __nv_bfloat16 h2v = __float2bfloat16(y2);
    oh[obase]       = h1;
    oh[obase + 128] = h2v;
    ol[obase]       = __float2bfloat16(y1 - __bfloat162float(h1));
    ol[obase + 128] = __float2bfloat16(y2 - __bfloat162float(h2v));
}

// =====================================================================
// HMMA GEMM: 2-stage pipeline, 80KB smem, 2 CTAs/SM.
// =====================================================================
#define STAGES 2
#define TILE_B 10240
#define STAGE_B (4 * TILE_B)
#define GEMM_SMEM (STAGES * STAGE_B)   // 81920

__device__ __forceinline__ void issue_stage(
    uint32_t sb, int c, int tid, int m0, int n0, int K,
    const __nv_bfloat16* Ah, const __nv_bfloat16* Al,
    const __nv_bfloat16* Bh, const __nv_bfloat16* Bl)
{
    uint32_t st = sb + (uint32_t)(c & 1) * STAGE_B;
    int k0 = c * 32;
#pragma unroll
    for (int half = 0; half < 2; half++) {
        int idx = tid + half * 256;
        int row = idx >> 2;
        int seg = idx & 3;
        uint32_t so = (uint32_t)(row * 80 + seg * 16);
        size_t ga = (size_t)(m0 + row) * K + k0 + seg * 8;
        size_t gb = (size_t)(n0 + row) * K + k0 + seg * 8;
        cp_async16(st + so,              Ah + ga);
        cp_async16(st + TILE_B + so,     Al + ga);
        cp_async16(st + 2 * TILE_B + so, Bh + gb);
        cp_async16(st + 3 * TILE_B + so, Bl + gb);
    }
    CP_COMMIT();
}

__global__ __launch_bounds__(256, 2) void gemm_hmma(
    const __nv_bfloat16* __restrict__ Ah, const __nv_bfloat16* __restrict__ Al,
    const __nv_bfloat16* __restrict__ Bh, const __nv_bfloat16* __restrict__ Bl,
    float* __restrict__ C, int M, int N, int K)
{
    extern __shared__ __align__(128) char smem[];
    const uint32_t sb = smem_u32(smem);
    const int tid = threadIdx.x;
    const int wid = tid >> 5, lane = tid & 31;
    const int wm = wid >> 2, wn = wid & 3;
    const int m0 = blockIdx.y * 128, n0 = blockIdx.x * 128;

    float acc[4][4][4];
#pragma unroll
    for (int mi = 0; mi < 4; mi++)
#pragma unroll
        for (int ni = 0; ni < 4; ni++)
#pragma unroll
            for (int r = 0; r < 4; r++) acc[mi][ni][r] = 0.f;

    const int NC = K >> 5;
    issue_stage(sb, 0, tid, m0, n0, K, Ah, Al, Bh, Bl);

    const uint32_t aoff = (uint32_t)((wm * 64 + (lane & 15)) * 80 +
                                     (lane >> 4) * 16);
    const uint32_t boff = (uint32_t)((wn * 32 + (lane & 7)) * 80 +
                                     ((lane >> 3) & 1) * 16);

    for (int c = 0; c < NC; c++) {
        if (c + 1 < NC)
            issue_stage(sb, c + 1, tid, m0, n0, K, Ah, Al, Bh, Bl);
        if (c + 1 < NC) CP_WAIT1(); else CP_WAIT0();
        __syncthreads();
        const uint32_t st = sb + (uint32_t)(c & 1) * STAGE_B;
        const uint32_t aA = st + aoff;
        const uint32_t aB = st + 2 * TILE_B + boff;

#pragma unroll
        for (int ks = 0; ks < 2; ks++) {
            uint32_t ah[4][4], al[4][4], bh[4][2], bl[4][2];
#pragma unroll
            for (int mi = 0; mi < 4; mi++)
                ldsm_x4(ah[mi], aA + mi * (16 * 80) + ks * 32);
#pragma unroll
            for (int ni = 0; ni < 4; ni++) {
                ldsm_x2(bh[ni], aB + ni * (8 * 80) + ks * 32);
                ldsm_x2(bl[ni], aB + TILE_B + ni * (8 * 80) + ks * 32);
            }
#pragma unroll
            for (int mi = 0; mi < 4; mi++)
#pragma unroll
                for (int ni = 0; ni < 4; ni++) {
                    mma16816(acc[mi][ni], ah[mi], bh[ni]);
                    mma16816(acc[mi][ni], ah[mi], bl[ni]);
                }
#pragma unroll
            for (int mi = 0; mi < 4; mi++)
                ldsm_x4(al[mi], aA + TILE_B + mi * (16 * 80) + ks * 32);
#pragma unroll
            for (int mi = 0; mi < 4; mi++)
#pragma unroll
                for (int ni = 0; ni < 4; ni++)
                    mma16816(acc[mi][ni], al[mi], bh[ni]);
        }
        __syncthreads();
    }

    const int gr = lane >> 2, cn = lane & 3;
#pragma unroll
    for (int mi = 0; mi < 4; mi++) {
        int r = m0 + wm * 64 + mi * 16 + gr;
#pragma unroll
        for (int ni = 0; ni < 4; ni++) {
            int col = n0 + wn * 32 + ni * 8 + cn * 2;
            *(float2*)(C + (size_t)r * N + col) =
                make_float2(acc[mi][ni][0], acc[mi][ni][1]);
            *(float2*)(C + (size_t)(r + 8) * N + col) =
                make_float2(acc[mi][ni][2], acc[mi][ni][3]);
        }
    }
}

// =====================================================================
// HMMA attention + coalesced probs writeback; heavy blocks scheduled first.
// =====================================================================
#define DP 528
#define PP 144
#define SM_QH 0
#define SM_QL (64 * DP)
#define SM_KH (2 * 64 * DP)
#define SM_KL (3 * 64 * DP)
#define SM_VH (4 * 64 * DP)
#define SM_VL (5 * 64 * DP)
#define SM_PH (6 * 64 * DP)
#define SM_PL (SM_PH + 64 * PP)
#define SM_LS (SM_PL + 64 * PP)
#define ATT_SMEM (SM_LS + 256)

__device__ __forceinline__ float capexp(float s, int ig, int jg) {
    float x = s * INV_CAP;
    x = fminf(fmaxf(x, -15.f), 15.f);
    float e = __expf(2.f * x);
    float t = (e - 1.f) / (e + 1.f) * CAP;
    bool win = (jg <= ig) && (ig - jg < 1024);
    return win ? __expf(t - CAP) : 0.f;
}

__global__ __launch_bounds__(256, 1) void attn_hmma(
    const __nv_bfloat16* __restrict__ qh, const __nv_bfloat16* __restrict__ ql,
    const __nv_bfloat16* __restrict__ kh, const __nv_bfloat16* __restrict__ kl,
    const __nv_bfloat16* __restrict__ vh, const __nv_bfloat16* __restrict__ vl,
    float* __restrict__ probs, float* __restrict__ attn_out,
    __nv_bfloat16* __restrict__ gath, __nv_bfloat16* __restrict__ gatl,
    float* __restrict__ linv)
{
    extern __shared__ __align__(128) char smem[];
    const uint32_t sb = smem_u32(smem);
    float* smls = (float*)(smem + SM_LS);
    const int tid = threadIdx.x, wid = tid >> 5, lane = tid & 31;
    const int wm = wid >> 1, wn = wid & 1;
    const int gr = lane >> 2, cn = lane & 3;
    // heavy (large q0) blocks first to shrink the last-wave tail
    const int q0 = (gridDim.x - 1 - blockIdx.x) * 64;
    const int h = blockIdx.y, b = blockIdx.z;
    const int hkv = h >> 1, bh = b * NH + h;

#pragma unroll
    for (int i = 0; i < 8; i++) {
        int seg = tid + i * 256;
        int r = seg >> 5, s = seg & 31;
        size_t g = ((size_t)(b * S_LEN + q0 + r)) * 2048 + h * 256 + s * 8;
        cp_async16(sb + SM_QH + r * DP + s * 16, qh + g);
        cp_async16(sb + SM_QL + r * DP + s * 16, ql + g);
    }
    CP_COMMIT();
    if (tid < 64) smls[tid] = 0.f;

    float acco[16][4];
#pragma unroll
    for (int i = 0; i < 16; i++)
#pragma unroll
        for (int r = 0; r < 4; r++) acco[i][r] = 0.f;

    const int kstart = max(0, q0 - 1024);
    const int qg0 = q0 + wm * 16 + gr;
    const int qg1 = qg0 + 8;

    for (int kt0 = kstart; kt0 <= q0; kt0 += 64) {
#pragma unroll
        for (int i = 0; i < 8; i++) {
            int seg = tid + i * 256;
            int r = seg >> 5, s = seg & 31;
            size_t g = ((size_t)(b * S_LEN + kt0 + r)) * 1024 + hkv * 256 + s * 8;
            cp_async16(sb + SM_KH + r * DP + s * 16, kh + g);
            cp_async16(sb + SM_KL + r * DP + s * 16, kl + g);
        }
        CP_COMMIT();
        CP_WAIT0();
        __syncthreads();

#pragma unroll
        for (int i = 0; i < 8; i++) {
            int seg = tid + i * 256;
            int r = seg >> 5, s = seg & 31;
            size_t g = ((size_t)(b * S_LEN + kt0 + r)) * 1024 + hkv * 256 + s * 8;
            cp_async16(sb + SM_VH + r * DP + s * 16, vh + g);
            cp_async16(sb + SM_VL + r * DP + s * 16, vl + g);
        }
        CP_COMMIT();

        // ---- S = Q K^T ----
        float sacc[4][4];
#pragma unroll
        for (int ni = 0; ni < 4; ni++)
#pragma unroll
            for (int r = 0; r < 4; r++) sacc[ni][r] = 0.f;

        const uint32_t qa = sb + SM_QH + (wm * 16 + (lane & 15)) * DP +
                            (lane >> 4) * 16;
        const uint32_t kb = sb + SM_KH + (wn * 32 + (lane & 7)) * DP +
                            ((lane >> 3) & 1) * 16;
#pragma unroll 4
        for (int kc = 0; kc < 16; kc++) {
            uint32_t ah[4], al[4], bhf[4][2], blf[4][2];
            ldsm_x4(ah, qa + kc * 32);
            ldsm_x4(al, qa + (SM_QL - SM_QH) + kc * 32);
#pragma unroll
            for (int ni = 0; ni < 4; ni++) {
                ldsm_x2(bhf[ni], kb + ni * (8 * DP) + kc * 32);
                ldsm_x2(blf[ni], kb + (SM_KL - SM_KH) + ni * (8 * DP) + kc * 32);
            }
#pragma unroll
            for (int ni = 0; ni < 4; ni++) {
                mma16816(sacc[ni], ah, bhf[ni]);
                mma16816(sacc[ni], ah, blf[ni]);
                mma16816(sacc[ni], al, bhf[ni]);
            }
        }

        // ---- softcap/exp, P split into smem, row sums ----
        float l0 = 0.f, l1 = 0.f;
#pragma unroll
        for (int ni = 0; ni < 4; ni++) {
            int keyb = kt0 + wn * 32 + ni * 8 + cn * 2;
            float p0 = capexp(sacc[ni][0], qg0, keyb);
            float p1 = capexp(sacc[ni][1], qg0, keyb + 1);
            float p2 = capexp(sacc[ni][2], qg1, keyb);
            float p3 = capexp(sacc[ni][3], qg1, keyb + 1);
            l0 += p0 + p1;
            l1 += p2 + p3;
            __nv_bfloat16 h0 = __float2bfloat16(p0), h1 = __float2bfloat16(p1);
            __nv_bfloat16 h2 = __float2bfloat16(p2), h3 = __float2bfloat16(p3);
            int pcol = (wn * 32 + ni * 8 + cn * 2) * 2;
            int pr0 = (wm * 16 + gr) * PP, pr1 = pr0 + 8 * PP;
            *(__nv_bfloat162*)(smem + SM_PH + pr0 + pcol) = __halves2bfloat162(h0, h1);
            *(__nv_bfloat162*)(smem + SM_PH + pr1 + pcol) = __halves2bfloat162(h2, h3);
            *(__nv_bfloat162*)(smem + SM_PL + pr0 + pcol) = __halves2bfloat162(
                __float2bfloat16(p0 - __bfloat162float(h0)),
                __float2bfloat16(p1 - __bfloat162float(h1)));
            *(__nv_bfloat162*)(smem + SM_PL + pr1 + pcol) = __halves2bfloat162(
                __float2bfloat16(p2 - __bfloat162float(h2)),
                __float2bfloat16(p3 - __bfloat162float(h3)));
        }
        l0 += __shfl_xor_sync(0xffffffffu, l0, 1);
        l0 += __shfl_xor_sync(0xffffffffu, l0, 2);
        l1 += __shfl_xor_sync(0xffffffffu, l1, 1);
        l1 += __shfl_xor_sync(0xffffffffu, l1, 2);
        if (cn == 0) {
            atomicAdd(&smls[wm * 16 + gr], l0);
            atomicAdd(&smls[wm * 16 + gr + 8], l1);
        }

        CP_WAIT0();
        __syncthreads();

        // ---- coalesced probs writeback from smem P (hi+lo) ----
#pragma unroll
        for (int i = 0; i < 4; i++) {
            int idx = tid + i * 256;
            int r = idx >> 4;
            int c4 = (idx & 15) * 4;
            uint2 vh2 = *(const uint2*)(smem + SM_PH + r * PP + c4 * 2);
            uint2 vl2 = *(const uint2*)(smem + SM_PL + r * PP + c4 * 2);
            float2 a0 = __bfloat1622float2(*(__nv_bfloat162*)&vh2.x);
            float2 a1 = __bfloat1622float2(*(__nv_bfloat162*)&vh2.y);
            float2 b0 = __bfloat1622float2(*(__nv_bfloat162*)&vl2.x);
            float2 b1 = __bfloat1622float2(*(__nv_bfloat162*)&vl2.y);
            float4 pv;
            pv.x = a0.x + b0.x; pv.y = a0.y + b0.y;
            pv.z = a1.x + b1.x; pv.w = a1.y + b1.y;
            *(float4*)(probs + ((size_t)bh * S_LEN + q0 + r) * S_LEN + kt0 + c4) = pv;
        }

        // ---- O += P~ V ----
        const uint32_t pa = sb + SM_PH + (wm * 16 + (lane & 15)) * PP +
                            (lane >> 4) * 16;
        const uint32_t vb = sb + SM_VH + (lane & 15) * DP +
                            (wn * 128) * 2 + (lane >> 4) * 16;
#pragma unroll
        for (int kk = 0; kk < 4; kk++) {
            uint32_t ph[4], pl[4];
            ldsm_x4(ph, pa + kk * 32);
            ldsm_x4(pl, pa + (SM_PL - SM_PH) + kk * 32);
#pragma unroll
            for (int nj = 0; nj < 8; nj++) {
                uint32_t vbh[4], vbl[4];
                uint32_t va = vb + kk * (16 * DP) + nj * 32;
                ldsm_x4t(vbh, va);
                ldsm_x4t(vbl, va + (SM_VL - SM_VH));
                mma16816(acco[nj * 2], ph, vbh);
                mma16816(acco[nj * 2], ph, vbl);
                mma16816(acco[nj * 2], pl, vbh);
                mma16816(acco[nj * 2 + 1], ph, vbh + 2);
                mma16816(acco[nj * 2 + 1], ph, vbl + 2);
                mma16816(acco[nj * 2 + 1], pl, vbh + 2);
            }
        }
        __syncthreads();
    }

    // ---- final epilogue ----
    if (tid < 64)
        linv[(size_t)bh * S_LEN + q0 + tid] = 1.f / smls[tid];
    float inv0 = 1.f / smls[wm * 16 + gr];
    float inv1 = 1.f / smls[wm * 16 + gr + 8];
#pragma unroll
    for (int ni = 0; ni < 16; ni++) {
        int col = wn * 128 + ni * 8 + cn * 2;
        float o0 = acco[ni][0] * inv0, o1 = acco[ni][1] * inv0;
        float o2 = acco[ni][2] * inv1, o3 = acco[ni][3] * inv1;
        *(float2*)(attn_out + ((size_t)bh * S_LEN + qg0) * 256 + col) =
            make_float2(o0, o1);
        *(float2*)(attn_out + ((size_t)bh * S_LEN + qg1) * 256 + col) =
            make_float2(o2, o3);
        size_t ga0 = ((size_t)(b * S_LEN) + qg0) * 2048 + h * 256 + col;
        size_t ga1 = ((size_t)(b * S_LEN) + qg1) * 2048 + h * 256 + col;
        __nv_bfloat16 h0 = __float2bfloat16(o0), h1 = __float2bfloat16(o1);
        __nv_bfloat16 h2 = __float2bfloat16(o2), h3 = __float2bfloat16(o3);
        *(__nv_bfloat162*)(gath + ga0) = __halves2bfloat162(h0, h1);
        *(__nv_bfloat162*)(gath + ga1) = __halves2bfloat162(h2, h3);
        *(__nv_bfloat162*)(gatl + ga0) = __halves2bfloat162(
            __float2bfloat16(o0 - __bfloat162float(h0)),
            __float2bfloat16(o1 - __bfloat162float(h1)));
        *(__nv_bfloat162*)(gatl + ga1) = __halves2bfloat162(
            __float2bfloat16(o2 - __bfloat162float(h2)),
            __float2bfloat16(o3 - __bfloat162float(h3)));
    }
}

// =====================================================================
// Full-row probs finalize: zero outside the band, scale inside.
// Replaces the big memset + banded norm (one pass, less DRAM traffic).
// =====================================================================
__global__ void norm_probs_full(float* __restrict__ probs,
                                const float* __restrict__ linv)
{
    int row = blockIdx.x;                 // (b*8+h)*2048 + i
    int i = row & (S_LEN - 1);
    float inv = linv[row];
    int lo = max(0, i - 1023);
    float4* p = (float4*)(probs + (size_t)row * S_LEN);
#pragma unroll
    for (int c = (int)threadIdx.x; c < 512; c += 256) {
        int c0 = c << 2;                  // first column of this float4
        float4 v;
        if (c0 + 3 < lo || c0 > i) {
            v = make_float4(0.f, 0.f, 0.f, 0.f);
        } else {
            v = p[c];
            v.x = (c0 >= lo && c0 <= i)         ? v.x * inv : 0.f;
            v.y = (c0 + 1 >= lo && c0 + 1 <= i) ? v.y * inv : 0.f;
            v.z = (c0 + 2 >= lo && c0 + 2 <= i) ? v.z * inv : 0.f;
            v.w = (c0 + 3 >= lo && c0 + 3 <= i) ? v.w * inv : 0.f;
        }
        p[c] = v;
    }
}

// =====================================================================
// Outputs: out[2,2048,2048] @0 | probs @8388608 | attn @75497472
// =====================================================================
extern "C" void kernel_launch(void* const* d_in, const int* in_sizes, int n_in,
                              void* d_out, int out_size)
{
    const float* hs = (const float*)d_in[0];
    const float* fc = (const float*)d_in[1];
    const float* fs = (const float*)d_in[2];
    const float* wq = (const float*)d_in[4];
    const float* wk = (const float*)d_in[5];
    const float* wv = (const float*)d_in[6];
    const float* wo = (const float*)d_in[7];

    float* out   = (float*)d_out;
    float* probs = out + 8388608ull;
    float* attn  = probs + 67108864ull;

    float *gqkv, *glinv;
    cudaGetSymbolAddress((void**)&gqkv, g_qkv);
    cudaGetSymbolAddress((void**)&glinv, g_linv);

    void *hsh, *hsl, *atth, *attl, *wh, *wl, *woh, *wol;
    void *qh, *ql, *kh, *kl, *vh, *vl;
    cudaGetSymbolAddress(&hsh, g_hs_h);  cudaGetSymbolAddress(&hsl, g_hs_l);
    cudaGetSymbolAddress(&atth, g_att_h); cudaGetSymbolAddress(&attl, g_att_l);
    cudaGetSymbolAddress(&wh, g_w_h);    cudaGetSymbolAddress(&wl, g_w_l);
    cudaGetSymbolAddress(&woh, g_wo_h);  cudaGetSymbolAddress(&wol, g_wo_l);
    cudaGetSymbolAddress(&qh, g_qh);     cudaGetSymbolAddress(&ql, g_ql);
    cudaGetSymbolAddress(&kh, g_kh);     cudaGetSymbolAddress(&kl, g_kl);
    cudaGetSymbolAddress(&vh, g_vh);     cudaGetSymbolAddress(&vl, g_vl);

    cudaFuncSetAttribute(gemm_hmma,
                         cudaFuncAttributeMaxDynamicSharedMemorySize, GEMM_SMEM);
    cudaFuncSetAttribute(attn_hmma,
                         cudaFuncAttributeMaxDynamicSharedMemorySize, ATT_SMEM);

    __nv_bfloat16* whb = (__nv_bfloat16*)wh;
    __nv_bfloat16* wlb = (__nv_bfloat16*)wl;

    // splits: hs + wq/wk/wv into the combined buffer + wo
    split_kernel<<<8192, 256>>>(hs, (__nv_bfloat16*)hsh, (__nv_bfloat16*)hsl, 2097152);
    split_kernel<<<4096, 256>>>(wq, whb,                 wlb,                 1048576);
    split_kernel<<<2048, 256>>>(wk, whb + 2048ull * 2048, wlb + 2048ull * 2048, 524288);
    split_kernel<<<2048, 256>>>(wv, whb + 3072ull * 2048, wlb + 3072ull * 2048, 524288);
    split_kernel<<<4096, 256>>>(wo, (__nv_bfloat16*)woh, (__nv_bfloat16*)wol, 1048576);

    // fused QKV projection: C[4096, 4096]
    gemm_hmma<<<dim3(32, 32), 256, GEMM_SMEM>>>(
        (const __nv_bfloat16*)hsh, (const __nv_bfloat16*)hsl,
        whb, wlb, gqkv, 4096, 4096, 2048);

    // RoPE + scale + split from the fused buffer; V split strided
    rope_split_kernel<<<16384, 256>>>(gqkv, 0, fc, fs, (__nv_bfloat16*)qh,
                                      (__nv_bfloat16*)ql, 8, QSCALE);
    rope_split_kernel<<<8192, 256>>>(gqkv, 2048, fc, fs, (__nv_bfloat16*)kh,
                                     (__nv_bfloat16*)kl, 4, 1.0f);
    split_strided_kernel<<<4096, 256>>>(gqkv, 3072, (__nv_bfloat16*)vh,
                                        (__nv_bfloat16*)vl);

    // attention (no probs memset needed; norm_probs_full zeros out-of-band)
    attn_hmma<<<dim3(32, 8, 2), 256, ATT_SMEM>>>(
        (const __nv_bfloat16*)qh, (const __nv_bfloat16*)ql,
        (const __nv_bfloat16*)kh, (const __nv_bfloat16*)kl,
        (const __nv_bfloat16*)vh, (const __nv_bfloat16*)vl,
        probs, attn, (__nv_bfloat16*)atth, (__nv_bfloat16*)attl, glinv);
    norm_probs_full<<<32768, 256>>>(probs, glinv);

    // output projection
    gemm_hmma<<<dim3(16, 32), 256, GEMM_SMEM>>>(
        (const __nv_bfloat16*)atth, (const __nv_bfloat16*)attl,
        (const __nv_bfloat16*)woh, (const __nv_bfloat16*)wol, out, 4096, 2048, 2048);
}